// round 3
// baseline (speedup 1.0000x reference)
#include <cuda_runtime.h>
#include <math.h>
#include <stdint.h>

// ---------------- problem constants ----------------
#define BSZ   512
#define SEQ   3
#define DM    1550          // D_MODEL
#define DS    16            // D_STATE
#define ED    3100          // EXPAND * D_MODEL
#define DTR   97            // DT_RANK
#define DBCN  129           // DTR + 2*DS
#define DBCP  132           // padded ldc for dbc (even, > DBCN)
#define DTWP  104           // padded ldb for dt_w (even, > DTR)
#define VOC   128
#define NR    (BSZ*SEQ)     // 1536 token rows
#define OE    256
#define EPSF  1e-5f

// ---------------- scratch (static device memory) ----------------
__device__ float g_h    [NR*DM];
__device__ float g_xn   [NR*DM];
__device__ float g_xz   [NR*2*ED];
__device__ float g_xc   [NR*ED];
__device__ float g_dbc  [NR*DBCP];
__device__ float g_delta[NR*ED];
__device__ float g_ys   [NR*ED];
__device__ float g_negA [ED*DS];
__device__ float g_dtw  [ED*DTWP];
__device__ float g_logit[NR*VOC];
__device__ float g_nrm  [NR*VOC];
__device__ float g_t    [NR*OE];
__device__ float g_part [384];
__device__ float g_stats[2];
__device__ float g_wesum[OE];

__device__ __forceinline__ float siluf(float v){ return v / (1.f + expf(-v)); }

__device__ __forceinline__ float tf32r(float x){
    uint32_t o;
    asm("cvt.rna.tf32.f32 %0, %1;" : "=r"(o) : "f"(x));
    return __uint_as_float(o);
}

__device__ __forceinline__ void mma_tf32(float c[4],
    uint32_t a0, uint32_t a1, uint32_t a2, uint32_t a3,
    uint32_t b0, uint32_t b1)
{
    asm volatile(
        "mma.sync.aligned.m16n8k8.row.col.f32.tf32.tf32.f32 "
        "{%0,%1,%2,%3}, {%4,%5,%6,%7}, {%8,%9}, {%0,%1,%2,%3};"
        : "+f"(c[0]), "+f"(c[1]), "+f"(c[2]), "+f"(c[3])
        : "r"(a0), "r"(a1), "r"(a2), "r"(a3), "r"(b0), "r"(b1));
}

// ---------------- TF32 tensor-core GEMM, double-buffered, packed-k smem ----------------
// C[M,N] (op)= A[M,K] * B[N,K]^T.  MT=4 -> BM=128 ; MT=2 -> BM=64. BN=128, BK=32.
// smem layout per tile row: float col p(k) = (k&3)*8 + (k>>2); float2 row stride 17.
// mode 0: C = acc ; mode 1: C += acc ; mode 2: C = softplus(acc + bias[n])
// Requirements: M % BM == 0; lda, ldb even; element gk+1 readable whenever gk < K.
template<int MT>
__global__ void __launch_bounds__(256) k_mma(
    const float* __restrict__ A, int lda,
    const float* __restrict__ B, int ldb,
    float* __restrict__ C, int ldc,
    int M, int N, int K,
    int mode, const float* __restrict__ bias)
{
    constexpr int BM = MT*32;
    extern __shared__ float2 sm[];
    float2* As2 = sm;                 // [2][BM][17]
    float2* Bs2 = sm + 2*BM*17;       // [2][128][17]

    const int tid  = threadIdx.x;
    const int wid  = tid >> 5, lane = tid & 31;
    const int g    = lane >> 2, tg = lane & 3;
    const int wm   = (wid >> 2) * (MT*16);
    const int wn   = (wid & 3) * 32;
    const int bm   = blockIdx.y * BM;
    const int bn   = blockIdx.x * 128;

    const int lk2  = tid & 15;        // float2 k-column within chunk
    const int lr   = tid >> 4;        // 0..15 tile row
    const int p0   = (lk2 & 1)*16 + (lk2 >> 1);   // permuted float col for k=2*lk2

    float acc[MT][4][4];
    #pragma unroll
    for (int mt = 0; mt < MT; mt++)
        #pragma unroll
        for (int nt = 0; nt < 4; nt++)
            #pragma unroll
            for (int i = 0; i < 4; i++) acc[mt][nt][i] = 0.f;

    float2 ra[MT*2], rb[8];
    const int nch = (K + 31) >> 5;

    // ---- prologue: load chunk 0 into regs ----
    {
        int gk = lk2*2;
        bool kok = gk < K, k1 = gk + 1 < K;
        #pragma unroll
        for (int p = 0; p < MT*2; p++){
            float2 v = make_float2(0.f, 0.f);
            if (kok){ v = *(const float2*)(A + (size_t)(bm + lr + p*16)*lda + gk); if(!k1) v.y = 0.f; }
            ra[p] = v;
        }
        #pragma unroll
        for (int p = 0; p < 8; p++){
            int gn = bn + lr + p*16;
            float2 v = make_float2(0.f, 0.f);
            if (gn < N && kok){ v = *(const float2*)(B + (size_t)gn*ldb + gk); if(!k1) v.y = 0.f; }
            rb[p] = v;
        }
    }

    for (int c = 0; c < nch; c++){
        // ---- store staged regs to smem buffer c&1 ----
        {
            float* Af = (float*)(As2 + (c & 1)*BM*17);
            float* Bf = (float*)(Bs2 + (c & 1)*128*17);
            #pragma unroll
            for (int p = 0; p < MT*2; p++){
                float* row = Af + (lr + p*16)*34;
                row[p0]     = tf32r(ra[p].x);
                row[p0 + 8] = tf32r(ra[p].y);
            }
            #pragma unroll
            for (int p = 0; p < 8; p++){
                float* row = Bf + (lr + p*16)*34;
                row[p0]     = tf32r(rb[p].x);
                row[p0 + 8] = tf32r(rb[p].y);
            }
        }
        __syncthreads();

        // ---- prefetch next chunk into regs ----
        if (c + 1 < nch){
            int gk = (c+1)*32 + lk2*2;
            bool kok = gk < K, k1 = gk + 1 < K;
            #pragma unroll
            for (int p = 0; p < MT*2; p++){
                float2 v = make_float2(0.f, 0.f);
                if (kok){ v = *(const float2*)(A + (size_t)(bm + lr + p*16)*lda + gk); if(!k1) v.y = 0.f; }
                ra[p] = v;
            }
            #pragma unroll
            for (int p = 0; p < 8; p++){
                int gn = bn + lr + p*16;
                float2 v = make_float2(0.f, 0.f);
                if (gn < N && kok){ v = *(const float2*)(B + (size_t)gn*ldb + gk); if(!k1) v.y = 0.f; }
                rb[p] = v;
            }
        }

        // ---- compute on buffer c&1 ----
        {
            const float2* Ab = As2 + (c & 1)*BM*17;
            const float2* Bb = Bs2 + (c & 1)*128*17;
            #pragma unroll
            for (int ks8 = 0; ks8 < 4; ks8++){
                uint32_t af[MT][4], bf[4][2];
                #pragma unroll
                for (int mt = 0; mt < MT; mt++){
                    const float2* pa = Ab + (wm + mt*16 + g)*17 + tg*4 + ks8;
                    float2 lo = pa[0];
                    float2 hi = pa[8*17];
                    af[mt][0] = __float_as_uint(lo.x);
                    af[mt][1] = __float_as_uint(hi.x);
                    af[mt][2] = __float_as_uint(lo.y);
                    af[mt][3] = __float_as_uint(hi.y);
                }
                #pragma unroll
                for (int nt = 0; nt < 4; nt++){
                    float2 bb = Bb[(wn + nt*8 + g)*17 + tg*4 + ks8];
                    bf[nt][0] = __float_as_uint(bb.x);
                    bf[nt][1] = __float_as_uint(bb.y);
                }
                #pragma unroll
                for (int mt = 0; mt < MT; mt++)
                    #pragma unroll
                    for (int nt = 0; nt < 4; nt++)
                        mma_tf32(acc[mt][nt], af[mt][0], af[mt][1], af[mt][2], af[mt][3],
                                 bf[nt][0], bf[nt][1]);
            }
        }
        __syncthreads();
    }

    // ---- epilogue ----
    #pragma unroll
    for (int mt = 0; mt < MT; mt++){
        int r0 = bm + wm + mt*16 + g;
        #pragma unroll
        for (int nt = 0; nt < 4; nt++){
            int cl = bn + wn + nt*8 + 2*tg;
            #pragma unroll
            for (int i = 0; i < 4; i++){
                int rr = r0 + (i >> 1)*8;
                int cc = cl + (i & 1);
                if (cc >= N) continue;
                float v = acc[mt][nt][i];
                size_t idx = (size_t)rr*ldc + cc;
                if (mode == 1){
                    v += C[idx];
                } else if (mode == 2){
                    float xv = v + bias[cc];
                    v = fmaxf(xv, 0.f) + log1pf(expf(-fabsf(xv)));
                }
                C[idx] = v;
            }
        }
    }
}

#define SMEM_MMA4 (2*(128+128)*17*sizeof(float2))   // 69632
#define SMEM_MMA2 (2*(64 +128)*17*sizeof(float2))   // 52224

// ---------------- input transpose: x(b,s,f,c,e) -> h(b*s, c*25+f*5+e) ----------------
__global__ void k_transpose_in(const float* __restrict__ x){
    int i = blockIdx.x*blockDim.x + threadIdx.x;
    if (i >= NR*DM) return;
    int n = i / DM, d = i % DM;
    int c = d / 25, r = d % 25, f = r / 5, e = r % 5;
    g_h[i] = x[((n*5 + f)*62 + c)*5 + e];
}

// ---------------- rmsnorm: g_h -> g_xn ----------------
__global__ void k_rmsnorm(const float* __restrict__ w){
    __shared__ float sh[33];
    int n = blockIdx.x;
    const float* row = g_h + (size_t)n*DM;
    float ss = 0.f;
    for (int d = threadIdx.x; d < DM; d += blockDim.x){ float v = row[d]; ss += v*v; }
    for (int o = 16; o; o >>= 1) ss += __shfl_down_sync(0xffffffffu, ss, o);
    if ((threadIdx.x & 31) == 0) sh[threadIdx.x >> 5] = ss;
    __syncthreads();
    if (threadIdx.x < 32){
        float v = (threadIdx.x < (int)(blockDim.x >> 5)) ? sh[threadIdx.x] : 0.f;
        for (int o = 16; o; o >>= 1) v += __shfl_down_sync(0xffffffffu, v, o);
        if (threadIdx.x == 0) sh[32] = rsqrtf(v / (float)DM + EPSF);
    }
    __syncthreads();
    float sc = sh[32];
    for (int d = threadIdx.x; d < DM; d += blockDim.x)
        g_xn[(size_t)n*DM + d] = row[d] * sc * w[d];
}

// ---------------- depthwise causal conv (S=3) + silu ----------------
__global__ void k_conv_silu(const float* __restrict__ cw, const float* __restrict__ cb){
    int e = blockIdx.x*blockDim.x + threadIdx.x;
    int b = blockIdx.y;
    if (e >= ED) return;
    size_t r0 = (size_t)(b*SEQ + 0)*(2*ED);
    size_t r1 = (size_t)(b*SEQ + 1)*(2*ED);
    size_t r2 = (size_t)(b*SEQ + 2)*(2*ED);
    float x0 = g_xz[r0 + e], x1 = g_xz[r1 + e], x2 = g_xz[r2 + e];
    float w1 = cw[e*4+1], w2 = cw[e*4+2], w3 = cw[e*4+3];
    float bb = cb[e];
    g_xc[(size_t)(b*SEQ + 0)*ED + e] = siluf(bb + w3*x0);
    g_xc[(size_t)(b*SEQ + 1)*ED + e] = siluf(bb + w2*x0 + w3*x1);
    g_xc[(size_t)(b*SEQ + 2)*ED + e] = siluf(bb + w1*x0 + w2*x1 + w3*x2);
}

// ---------------- negA = -exp(A_log[l]) ----------------
__global__ void k_negA(const float* __restrict__ Alog){
    int i = blockIdx.x*blockDim.x + threadIdx.x;
    if (i < ED*DS) g_negA[i] = -expf(Alog[i]);
}

// ---------------- pad dt_w[l] (ED x 97) -> g_dtw (ED x 104) ----------------
__global__ void k_padw(const float* __restrict__ src){
    int i = blockIdx.x*blockDim.x + threadIdx.x;
    if (i >= ED*DTR) return;
    g_dtw[(i/DTR)*DTWP + (i%DTR)] = src[i];
}

// ---------------- fused SSM scan (S=3), + D*xc, * silu(z) ----------------
__global__ void k_scan(const float* __restrict__ Dp){
    __shared__ float sB[SEQ][DS], sC[SEQ][DS];
    int e = blockIdx.x*blockDim.x + threadIdx.x;
    int b = blockIdx.y;
    int t = threadIdx.x;
    if (t < SEQ*DS){
        int s = t / DS, n = t % DS;
        size_t base = (size_t)(b*SEQ + s)*DBCP + DTR;
        sB[s][n] = g_dbc[base + n];
        sC[s][n] = g_dbc[base + DS + n];
    }
    __syncthreads();
    if (e >= ED) return;

    float nA[DS], hst[DS];
    #pragma unroll
    for (int n = 0; n < DS; n++){ nA[n] = g_negA[e*DS + n]; hst[n] = 0.f; }
    float dpe = Dp[e];

    #pragma unroll
    for (int s = 0; s < SEQ; s++){
        size_t row = (size_t)(b*SEQ + s);
        float d   = g_delta[row*ED + e];
        float xcv = g_xc[row*ED + e];
        float dx  = d * xcv;
        float y = 0.f;
        #pragma unroll
        for (int n = 0; n < DS; n++){
            float dA = __expf(d * nA[n]);
            hst[n] = dA*hst[n] + dx*sB[s][n];
            y = fmaf(hst[n], sC[s][n], y);
        }
        y += dpe * xcv;
        float z = g_xz[row*(2*ED) + ED + e];
        g_ys[row*ED + e] = y * siluf(z);
    }
}

// ---------------- logits mean/var (deterministic 2-pass) ----------------
__global__ void k_red1(){
    __shared__ float s1[32], s2[32];
    int base = blockIdx.x * 1024;
    float s = 0.f, q = 0.f;
    for (int i = threadIdx.x; i < 1024; i += 256){
        float v = g_logit[base + i];
        s += v; q += v*v;
    }
    for (int o = 16; o; o >>= 1){
        s += __shfl_down_sync(0xffffffffu, s, o);
        q += __shfl_down_sync(0xffffffffu, q, o);
    }
    if ((threadIdx.x & 31) == 0){ s1[threadIdx.x>>5] = s; s2[threadIdx.x>>5] = q; }
    __syncthreads();
    if (threadIdx.x < 32){
        float a = (threadIdx.x < 8) ? s1[threadIdx.x] : 0.f;
        float c = (threadIdx.x < 8) ? s2[threadIdx.x] : 0.f;
        for (int o = 4; o; o >>= 1){
            a += __shfl_down_sync(0xffffffffu, a, o);
            c += __shfl_down_sync(0xffffffffu, c, o);
        }
        if (threadIdx.x == 0){ g_part[blockIdx.x*2] = a; g_part[blockIdx.x*2+1] = c; }
    }
}

__global__ void k_red2(){
    __shared__ float s1[32], s2[32];
    float s = 0.f, q = 0.f;
    for (int i = threadIdx.x; i < 192; i += 256){ s += g_part[i*2]; q += g_part[i*2+1]; }
    for (int o = 16; o; o >>= 1){
        s += __shfl_down_sync(0xffffffffu, s, o);
        q += __shfl_down_sync(0xffffffffu, q, o);
    }
    if ((threadIdx.x & 31) == 0){ s1[threadIdx.x>>5] = s; s2[threadIdx.x>>5] = q; }
    __syncthreads();
    if (threadIdx.x == 0){
        float a = 0.f, c = 0.f;
        for (int i = 0; i < 8; i++){ a += s1[i]; c += s2[i]; }
        const float T = (float)(NR*VOC);
        float mean = a / T;
        float var  = c / T - mean*mean;
        g_stats[0] = mean;
        g_stats[1] = rsqrtf(var + EPSF);
    }
}

__global__ void k_nrm(){
    int i = blockIdx.x*blockDim.x + threadIdx.x;
    if (i < NR*VOC) g_nrm[i] = (g_logit[i] - g_stats[0]) * g_stats[1];
}

__global__ void k_wesum(const float* __restrict__ emb_w){
    int o = threadIdx.x;
    float s = 0.f;
    for (int v = 0; v < VOC; v++) s += emb_w[o*VOC + v];
    g_wesum[o] = s;
}

// ---------------- final expand over f: out(b,f,s,o) ----------------
__global__ void k_final(const float* __restrict__ bnw, const float* __restrict__ bnb,
                        const float* __restrict__ embb, float* __restrict__ out){
    int i = blockIdx.x*blockDim.x + threadIdx.x;
    const int total = BSZ*5*SEQ*OE;
    if (i >= total) return;
    int o = i & 255;
    int s = (i >> 8) % SEQ;
    int f = (i / (OE*SEQ)) % 5;
    int b = i / (OE*SEQ*5);
    int n = b*SEQ + s;
    out[i] = bnw[f]*g_t[(size_t)n*OE + o] + bnb[f]*g_wesum[o] + embb[o];
}

// ---------------- launch ----------------
extern "C" void kernel_launch(void* const* d_in, const int* in_sizes, int n_in,
                              void* d_out, int out_size)
{
    const float* x        = (const float*)d_in[0];
    const float* in_w     = (const float*)d_in[1];
    const float* conv_w   = (const float*)d_in[2];
    const float* conv_b   = (const float*)d_in[3];
    const float* xp_w     = (const float*)d_in[4];
    const float* dt_w     = (const float*)d_in[5];
    const float* dt_b     = (const float*)d_in[6];
    const float* A_log    = (const float*)d_in[7];
    const float* D_param  = (const float*)d_in[8];
    const float* out_w    = (const float*)d_in[9];
    const float* norm_w   = (const float*)d_in[10];
    const float* normf_w  = (const float*)d_in[11];
    const float* lm_w     = (const float*)d_in[12];
    const float* bn_w     = (const float*)d_in[13];
    const float* bn_b     = (const float*)d_in[14];
    const float* emb_w    = (const float*)d_in[15];
    const float* emb_b    = (const float*)d_in[16];
    float* out = (float*)d_out;

    // opt-in to >48KB dynamic smem (attribute set, not a stream op; capture-safe)
    cudaFuncSetAttribute(k_mma<4>, cudaFuncAttributeMaxDynamicSharedMemorySize, (int)SMEM_MMA4);
    cudaFuncSetAttribute(k_mma<2>, cudaFuncAttributeMaxDynamicSharedMemorySize, (int)SMEM_MMA2);

    float *pxn, *pxz, *pxc, *pdbc, *pdelta, *pys, *ph, *plog, *pnrm, *pt, *pdtw;
    cudaGetSymbolAddress((void**)&ph,     g_h);
    cudaGetSymbolAddress((void**)&pxn,    g_xn);
    cudaGetSymbolAddress((void**)&pxz,    g_xz);
    cudaGetSymbolAddress((void**)&pxc,    g_xc);
    cudaGetSymbolAddress((void**)&pdbc,   g_dbc);
    cudaGetSymbolAddress((void**)&pdelta, g_delta);
    cudaGetSymbolAddress((void**)&pys,    g_ys);
    cudaGetSymbolAddress((void**)&plog,   g_logit);
    cudaGetSymbolAddress((void**)&pnrm,   g_nrm);
    cudaGetSymbolAddress((void**)&pt,     g_t);
    cudaGetSymbolAddress((void**)&pdtw,   g_dtw);

    k_transpose_in<<<(NR*DM + 255)/256, 256>>>(x);

    for (int l = 0; l < 2; l++){
        // rmsnorm(h) -> xn
        k_rmsnorm<<<NR, 256>>>(norm_w + l*DM);
        // xz = xn @ in_w^T   (1536 x 6200, K=1550)
        k_mma<4><<<dim3(49, 12), 256, SMEM_MMA4>>>(
            pxn, DM, in_w + (size_t)l*2*ED*DM, DM, pxz, 2*ED, NR, 2*ED, DM, 0, nullptr);
        // conv + silu -> xc
        k_conv_silu<<<dim3((ED+255)/256, BSZ), 256>>>(conv_w + (size_t)l*ED*4, conv_b + l*ED);
        // dbc = xc @ xp_w^T  (1536 x 129, K=3100), ldc padded to 132
        k_mma<2><<<dim3(2, 24), 256, SMEM_MMA2>>>(
            pxc, ED, xp_w + (size_t)l*DBCN*ED, ED, pdbc, DBCP, NR, DBCN, ED, 0, nullptr);
        // pad dt_w for even-stride loads
        k_padw<<<(ED*DTR + 255)/256, 256>>>(dt_w + (size_t)l*ED*DTR);
        // delta = softplus(dt @ dt_w^T + dt_b)  (1536 x 3100, K=97)
        k_mma<4><<<dim3(25, 12), 256, SMEM_MMA4>>>(
            pdbc, DBCP, pdtw, DTWP, pdelta, ED, NR, ED, DTR, 2, dt_b + l*ED);
        // negA
        k_negA<<<(ED*DS + 255)/256, 256>>>(A_log + (size_t)l*ED*DS);
        // scan -> ys
        k_scan<<<dim3((ED+255)/256, BSZ), 256>>>(D_param + l*ED);
        // h += ys @ out_w^T  (1536 x 1550, K=3100)
        k_mma<4><<<dim3(13, 12), 256, SMEM_MMA4>>>(
            pys, ED, out_w + (size_t)l*DM*ED, ED, ph, DM, NR, DM, ED, 1, nullptr);
    }

    // final rmsnorm -> xn
    k_rmsnorm<<<NR, 256>>>(normf_w);
    // logits = xn @ lm_w^T  (1536 x 128, K=1550)
    k_mma<2><<<dim3(1, 24), 256, SMEM_MMA2>>>(
        pxn, DM, lm_w, DM, plog, VOC, NR, VOC, DM, 0, nullptr);
    // global mean/var of logits (per-f stats identical: f is a broadcast axis)
    k_red1<<<192, 256>>>();
    k_red2<<<1, 256>>>();
    k_nrm<<<(NR*VOC + 255)/256, 256>>>();
    // t = nrm @ emb_w^T  (1536 x 256, K=128)
    k_mma<2><<<dim3(2, 24), 256, SMEM_MMA2>>>(
        pnrm, VOC, emb_w, VOC, pt, OE, NR, OE, VOC, 0, nullptr);
    k_wesum<<<1, 256>>>(emb_w);
    // out[b,f,s,o] = bn_w[f]*t[n,o] + bn_b[f]*wesum[o] + emb_b[o]
    k_final<<<(BSZ*5*SEQ*OE + 255)/256, 256>>>(bn_w, bn_b, emb_b, out);
}

// round 4
// speedup vs baseline: 1.7825x; 1.7825x over previous
#include <cuda_runtime.h>
#include <math.h>
#include <stdint.h>

// ---------------- problem constants ----------------
#define BSZ   512
#define SEQ   3
#define DM    1550          // D_MODEL
#define DS    16            // D_STATE
#define ED    3100          // EXPAND * D_MODEL
#define DTR   97            // DT_RANK
#define DBCN  129           // DTR + 2*DS
#define DBCP  132           // padded ldc for dbc
#define DTWP  104           // padded K for dt GEMM (zeros beyond DTR)
#define VOC   128
#define NR    (BSZ*SEQ)     // 1536 token rows
#define OE    256
#define EPSF  1e-5f

#define N_INW  (2*2*ED*DM)   // 19,220,000
#define N_XPW  (2*DBCN*ED)   // 799,800
#define N_OUTW (2*DM*ED)     // 9,610,000
#define N_LMW  (VOC*DM)      // 198,400
#define N_EMBW (OE*VOC)      // 32,768

// ---------------- scratch (static device memory; zero-initialized) ----------------
__device__ __align__(256) float g_h    [NR*DM];
__device__ __align__(256) float g_xn   [NR*DM];
__device__ __align__(256) float g_xz   [NR*2*ED];
__device__ __align__(256) float g_xc   [NR*ED];       // exact (scan)
__device__ __align__(256) float g_xct  [NR*ED];       // tf32-rounded (GEMM A)
__device__ __align__(256) float g_dbc  [NR*DBCP];
__device__ __align__(256) float g_delta[NR*ED];
__device__ __align__(256) float g_ys   [NR*ED];
__device__ __align__(256) float g_negA [2*ED*DS];
__device__ __align__(256) float g_dtw  [2*ED*DTWP];
__device__ __align__(256) float g_logit[NR*VOC];
__device__ __align__(256) float g_nrm  [NR*VOC];
__device__ __align__(256) float g_t    [NR*OE];
__device__ __align__(256) float g_inw  [N_INW];
__device__ __align__(256) float g_xpw  [N_XPW];
__device__ __align__(256) float g_outw [N_OUTW];
__device__ __align__(256) float g_lmw  [N_LMW];
__device__ __align__(256) float g_embw [N_EMBW];
__device__ float g_part [384];
__device__ float g_stats[2];
__device__ float g_wesum[OE];

__device__ __forceinline__ float siluf(float v){ return v / (1.f + expf(-v)); }

__device__ __forceinline__ float tf32r(float x){
    uint32_t o;
    asm("cvt.rna.tf32.f32 %0, %1;" : "=r"(o) : "f"(x));
    return __uint_as_float(o);
}

__device__ __forceinline__ void mma_tf32(float c[4],
    uint32_t a0, uint32_t a1, uint32_t a2, uint32_t a3,
    uint32_t b0, uint32_t b1)
{
    asm volatile(
        "mma.sync.aligned.m16n8k8.row.col.f32.tf32.tf32.f32 "
        "{%0,%1,%2,%3}, {%4,%5,%6,%7}, {%8,%9}, {%0,%1,%2,%3};"
        : "+f"(c[0]), "+f"(c[1]), "+f"(c[2]), "+f"(c[3])
        : "r"(a0), "r"(a1), "r"(a2), "r"(a3), "r"(b0), "r"(b1));
}

__device__ __forceinline__ void cpa8(uint32_t sdst, const float* gsrc, int nbytes){
    asm volatile("cp.async.ca.shared.global [%0], [%1], 8, %2;"
                 :: "r"(sdst), "l"(gsrc), "r"(nbytes));
}

// ---------------- TF32 GEMM, cp.async double-buffered ----------------
// C[M,N] (op)= A[M,K] * B[N,K]^T.  MT=4 -> BM=128 ; MT=2 -> BM=64. BN=128, BK=32.
// smem rows [m][k] stride 36 floats. Operands PRE-ROUNDED to tf32.
// Requirements: M % BM == 0; lda, ldb, K even.
// mode 0: C = acc ; 1: C += acc ; 2: C = softplus(acc + bias[n]) ;
// mode 3: C = acc, tf32-rounded for cols < DTR (dbc GEMM: dt cols feed next GEMM).
template<int MT>
__global__ void __launch_bounds__(256, 2) k_mma(
    const float* __restrict__ A, int lda,
    const float* __restrict__ B, int ldb,
    float* __restrict__ C, int ldc,
    int M, int N, int K,
    int mode, const float* __restrict__ bias)
{
    constexpr int BM = MT*32;
    extern __shared__ float smf[];
    float* As = smf;                 // [2][BM][36]
    float* Bs = smf + 2*BM*36;       // [2][128][36]

    const int tid  = threadIdx.x;
    const int wid  = tid >> 5, lane = tid & 31;
    const int g    = lane >> 2, tg = lane & 3;
    const int wm   = (wid >> 2) * (MT*16);
    const int wn   = (wid & 3) * 32;
    const int bm   = blockIdx.y * BM;
    const int bn   = blockIdx.x * 128;
    const int lk2  = tid & 15;        // float2 k-col
    const int lr   = tid >> 4;        // 0..15 row

    const uint32_t sA = (uint32_t)__cvta_generic_to_shared(As);
    const uint32_t sB = (uint32_t)__cvta_generic_to_shared(Bs);

    float acc[MT][4][4];
    #pragma unroll
    for (int mt = 0; mt < MT; mt++)
        #pragma unroll
        for (int nt = 0; nt < 4; nt++)
            #pragma unroll
            for (int i = 0; i < 4; i++) acc[mt][nt][i] = 0.f;

    const int nch = (K + 31) >> 5;

    auto issue = [&](int c){
        const int gk = c*32 + lk2*2;
        const int s  = c & 1;
        const int pk = (gk < K) ? 8 : 0;
        uint32_t da = sA + (uint32_t)(s*BM*36 + lr*36 + 2*lk2)*4u;
        const float* ga = A + (size_t)(bm + lr)*lda + (gk < K ? gk : 0);
        #pragma unroll
        for (int p = 0; p < MT*2; p++)
            cpa8(da + (uint32_t)(p*16*36*4), ga + (size_t)p*16*lda, pk);
        uint32_t db = sB + (uint32_t)(s*128*36 + lr*36 + 2*lk2)*4u;
        #pragma unroll
        for (int p = 0; p < 8; p++){
            int gn = bn + lr + p*16;
            int pb = (gn < N) ? pk : 0;
            const float* gb = B + (size_t)(gn < N ? gn : 0)*ldb + (gk < K ? gk : 0);
            cpa8(db + (uint32_t)(p*16*36*4), gb, pb);
        }
        asm volatile("cp.async.commit_group;");
    };

    issue(0);
    for (int c = 0; c < nch; c++){
        if (c + 1 < nch){
            issue(c + 1);
            asm volatile("cp.async.wait_group 1;");
        } else {
            asm volatile("cp.async.wait_group 0;");
        }
        __syncthreads();

        const float* Ab = As + (c & 1)*BM*36;
        const float* Bb = Bs + (c & 1)*128*36;
        #pragma unroll
        for (int ks8 = 0; ks8 < 4; ks8++){
            const int ks = ks8*8;
            uint32_t af[MT][4], bf[4][2];
            #pragma unroll
            for (int mt = 0; mt < MT; mt++){
                const float* pa = Ab + (wm + mt*16 + g)*36 + ks + tg;
                af[mt][0] = __float_as_uint(pa[0]);
                af[mt][1] = __float_as_uint(pa[8*36]);
                af[mt][2] = __float_as_uint(pa[4]);
                af[mt][3] = __float_as_uint(pa[8*36 + 4]);
            }
            #pragma unroll
            for (int nt = 0; nt < 4; nt++){
                const float* pb = Bb + (wn + nt*8 + g)*36 + ks + tg;
                bf[nt][0] = __float_as_uint(pb[0]);
                bf[nt][1] = __float_as_uint(pb[4]);
            }
            #pragma unroll
            for (int mt = 0; mt < MT; mt++)
                #pragma unroll
                for (int nt = 0; nt < 4; nt++)
                    mma_tf32(acc[mt][nt], af[mt][0], af[mt][1], af[mt][2], af[mt][3],
                             bf[nt][0], bf[nt][1]);
        }
        __syncthreads();
    }

    // ---- epilogue ----
    #pragma unroll
    for (int mt = 0; mt < MT; mt++){
        int r0 = bm + wm + mt*16 + g;
        #pragma unroll
        for (int nt = 0; nt < 4; nt++){
            int cl = bn + wn + nt*8 + 2*tg;
            #pragma unroll
            for (int i = 0; i < 4; i++){
                int rr = r0 + (i >> 1)*8;
                int cc = cl + (i & 1);
                if (cc >= N) continue;
                float v = acc[mt][nt][i];
                size_t idx = (size_t)rr*ldc + cc;
                if (mode == 1){
                    v += C[idx];
                } else if (mode == 2){
                    float xv = v + bias[cc];
                    v = fmaxf(xv, 0.f) + log1pf(expf(-fabsf(xv)));
                } else if (mode == 3){
                    if (cc < DTR) v = tf32r(v);
                }
                C[idx] = v;
            }
        }
    }
}

#define SMEM_MMA4 (2*(128+128)*36*sizeof(float))   // 73728
#define SMEM_MMA2 (2*(64 +128)*36*sizeof(float))   // 55296

// ---------------- tf32 conversion (weights) ----------------
__global__ void k_cvt(const float* __restrict__ src, float* __restrict__ dst, int n){
    int i = blockIdx.x*blockDim.x + threadIdx.x;
    if (i < n) dst[i] = tf32r(src[i]);
}

// ---------------- input transpose ----------------
__global__ void k_transpose_in(const float* __restrict__ x){
    int i = blockIdx.x*blockDim.x + threadIdx.x;
    if (i >= NR*DM) return;
    int n = i / DM, d = i % DM;
    int c = d / 25, r = d % 25, f = r / 5, e = r % 5;
    g_h[i] = x[((n*5 + f)*62 + c)*5 + e];
}

// ---------------- rmsnorm: g_h -> g_xn (tf32-rounded, GEMM A operand) ----------------
__global__ void k_rmsnorm(const float* __restrict__ w){
    __shared__ float sh[33];
    int n = blockIdx.x;
    const float* row = g_h + (size_t)n*DM;
    float ss = 0.f;
    for (int d = threadIdx.x; d < DM; d += blockDim.x){ float v = row[d]; ss += v*v; }
    for (int o = 16; o; o >>= 1) ss += __shfl_down_sync(0xffffffffu, ss, o);
    if ((threadIdx.x & 31) == 0) sh[threadIdx.x >> 5] = ss;
    __syncthreads();
    if (threadIdx.x < 32){
        float v = (threadIdx.x < (int)(blockDim.x >> 5)) ? sh[threadIdx.x] : 0.f;
        for (int o = 16; o; o >>= 1) v += __shfl_down_sync(0xffffffffu, v, o);
        if (threadIdx.x == 0) sh[32] = rsqrtf(v / (float)DM + EPSF);
    }
    __syncthreads();
    float sc = sh[32];
    for (int d = threadIdx.x; d < DM; d += blockDim.x)
        g_xn[(size_t)n*DM + d] = tf32r(row[d] * sc * w[d]);
}

// ---------------- depthwise causal conv + silu; exact + rounded copies ----------------
__global__ void k_conv_silu(const float* __restrict__ cw, const float* __restrict__ cb){
    int e = blockIdx.x*blockDim.x + threadIdx.x;
    int b = blockIdx.y;
    if (e >= ED) return;
    size_t r0 = (size_t)(b*SEQ + 0)*(2*ED);
    size_t r1 = (size_t)(b*SEQ + 1)*(2*ED);
    size_t r2 = (size_t)(b*SEQ + 2)*(2*ED);
    float x0 = g_xz[r0 + e], x1 = g_xz[r1 + e], x2 = g_xz[r2 + e];
    float w1 = cw[e*4+1], w2 = cw[e*4+2], w3 = cw[e*4+3];
    float bb = cb[e];
    float y0 = siluf(bb + w3*x0);
    float y1 = siluf(bb + w2*x0 + w3*x1);
    float y2 = siluf(bb + w1*x0 + w2*x1 + w3*x2);
    g_xc [(size_t)(b*SEQ + 0)*ED + e] = y0;  g_xct[(size_t)(b*SEQ + 0)*ED + e] = tf32r(y0);
    g_xc [(size_t)(b*SEQ + 1)*ED + e] = y1;  g_xct[(size_t)(b*SEQ + 1)*ED + e] = tf32r(y1);
    g_xc [(size_t)(b*SEQ + 2)*ED + e] = y2;  g_xct[(size_t)(b*SEQ + 2)*ED + e] = tf32r(y2);
}

// ---------------- negA (both layers) ----------------
__global__ void k_negA(const float* __restrict__ Alog){
    int i = blockIdx.x*blockDim.x + threadIdx.x;
    if (i < 2*ED*DS) g_negA[i] = -expf(Alog[i]);
}

// ---------------- pad+round dt_w (both layers) -> g_dtw[2][ED][DTWP] ----------------
__global__ void k_padw(const float* __restrict__ dt_w){
    int i = blockIdx.x*blockDim.x + threadIdx.x;
    if (i >= 2*ED*DTWP) return;
    int c = i % DTWP;
    int r = (i / DTWP) % ED;
    int l = i / (ED*DTWP);
    g_dtw[i] = (c < DTR) ? tf32r(dt_w[((size_t)l*ED + r)*DTR + c]) : 0.f;
}

// ---------------- fused SSM scan (S=3), + D*xc, * silu(z); tf32-rounded out ----------------
__global__ void k_scan(const float* __restrict__ nAbase, const float* __restrict__ Dp){
    __shared__ float sB[SEQ][DS], sC[SEQ][DS];
    int e = blockIdx.x*blockDim.x + threadIdx.x;
    int b = blockIdx.y;
    int t = threadIdx.x;
    if (t < SEQ*DS){
        int s = t / DS, n = t % DS;
        size_t base = (size_t)(b*SEQ + s)*DBCP + DTR;
        sB[s][n] = g_dbc[base + n];
        sC[s][n] = g_dbc[base + DS + n];
    }
    __syncthreads();
    if (e >= ED) return;

    float nA[DS], hst[DS];
    #pragma unroll
    for (int n = 0; n < DS; n++){ nA[n] = nAbase[e*DS + n]; hst[n] = 0.f; }
    float dpe = Dp[e];

    #pragma unroll
    for (int s = 0; s < SEQ; s++){
        size_t row = (size_t)(b*SEQ + s);
        float d   = g_delta[row*ED + e];
        float xcv = g_xc[row*ED + e];
        float dx  = d * xcv;
        float y = 0.f;
        #pragma unroll
        for (int n = 0; n < DS; n++){
            float dA = __expf(d * nA[n]);
            hst[n] = dA*hst[n] + dx*sB[s][n];
            y = fmaf(hst[n], sC[s][n], y);
        }
        y += dpe * xcv;
        float z = g_xz[row*(2*ED) + ED + e];
        g_ys[row*ED + e] = tf32r(y * siluf(z));
    }
}

// ---------------- logits mean/var (deterministic 2-pass) ----------------
__global__ void k_red1(){
    __shared__ float s1[32], s2[32];
    int base = blockIdx.x * 1024;
    float s = 0.f, q = 0.f;
    for (int i = threadIdx.x; i < 1024; i += 256){
        float v = g_logit[base + i];
        s += v; q += v*v;
    }
    for (int o = 16; o; o >>= 1){
        s += __shfl_down_sync(0xffffffffu, s, o);
        q += __shfl_down_sync(0xffffffffu, q, o);
    }
    if ((threadIdx.x & 31) == 0){ s1[threadIdx.x>>5] = s; s2[threadIdx.x>>5] = q; }
    __syncthreads();
    if (threadIdx.x < 32){
        float a = (threadIdx.x < 8) ? s1[threadIdx.x] : 0.f;
        float c = (threadIdx.x < 8) ? s2[threadIdx.x] : 0.f;
        for (int o = 4; o; o >>= 1){
            a += __shfl_down_sync(0xffffffffu, a, o);
            c += __shfl_down_sync(0xffffffffu, c, o);
        }
        if (threadIdx.x == 0){ g_part[blockIdx.x*2] = a; g_part[blockIdx.x*2+1] = c; }
    }
}

__global__ void k_red2(){
    __shared__ float s1[32], s2[32];
    float s = 0.f, q = 0.f;
    for (int i = threadIdx.x; i < 192; i += 256){ s += g_part[i*2]; q += g_part[i*2+1]; }
    for (int o = 16; o; o >>= 1){
        s += __shfl_down_sync(0xffffffffu, s, o);
        q += __shfl_down_sync(0xffffffffu, q, o);
    }
    if ((threadIdx.x & 31) == 0){ s1[threadIdx.x>>5] = s; s2[threadIdx.x>>5] = q; }
    __syncthreads();
    if (threadIdx.x == 0){
        float a = 0.f, c = 0.f;
        for (int i = 0; i < 8; i++){ a += s1[i]; c += s2[i]; }
        const float T = (float)(NR*VOC);
        float mean = a / T;
        float var  = c / T - mean*mean;
        g_stats[0] = mean;
        g_stats[1] = rsqrtf(var + EPSF);
    }
}

__global__ void k_nrm(){
    int i = blockIdx.x*blockDim.x + threadIdx.x;
    if (i < NR*VOC) g_nrm[i] = tf32r((g_logit[i] - g_stats[0]) * g_stats[1]);
}

__global__ void k_wesum(const float* __restrict__ emb_w){
    int o = threadIdx.x;
    float s = 0.f;
    for (int v = 0; v < VOC; v++) s += emb_w[o*VOC + v];
    g_wesum[o] = s;
}

// ---------------- final expand over f ----------------
__global__ void k_final(const float* __restrict__ bnw, const float* __restrict__ bnb,
                        const float* __restrict__ embb, float* __restrict__ out){
    int i = blockIdx.x*blockDim.x + threadIdx.x;
    const int total = BSZ*5*SEQ*OE;
    if (i >= total) return;
    int o = i & 255;
    int s = (i >> 8) % SEQ;
    int f = (i / (OE*SEQ)) % 5;
    int b = i / (OE*SEQ*5);
    int n = b*SEQ + s;
    out[i] = bnw[f]*g_t[(size_t)n*OE + o] + bnb[f]*g_wesum[o] + embb[o];
}

// ---------------- launch ----------------
extern "C" void kernel_launch(void* const* d_in, const int* in_sizes, int n_in,
                              void* d_out, int out_size)
{
    const float* x        = (const float*)d_in[0];
    const float* in_w     = (const float*)d_in[1];
    const float* conv_w   = (const float*)d_in[2];
    const float* conv_b   = (const float*)d_in[3];
    const float* xp_w     = (const float*)d_in[4];
    const float* dt_w     = (const float*)d_in[5];
    const float* dt_b     = (const float*)d_in[6];
    const float* A_log    = (const float*)d_in[7];
    const float* D_param  = (const float*)d_in[8];
    const float* out_w    = (const float*)d_in[9];
    const float* norm_w   = (const float*)d_in[10];
    const float* normf_w  = (const float*)d_in[11];
    const float* lm_w     = (const float*)d_in[12];
    const float* bn_w     = (const float*)d_in[13];
    const float* bn_b     = (const float*)d_in[14];
    const float* emb_w    = (const float*)d_in[15];
    const float* emb_b    = (const float*)d_in[16];
    float* out = (float*)d_out;

    cudaFuncSetAttribute(k_mma<4>, cudaFuncAttributeMaxDynamicSharedMemorySize, (int)SMEM_MMA4);
    cudaFuncSetAttribute(k_mma<2>, cudaFuncAttributeMaxDynamicSharedMemorySize, (int)SMEM_MMA2);

    float *pxn, *pxz, *pxct, *pdbc, *pdelta, *pys, *ph, *plog, *pnrm, *pt;
    float *pdtw, *pnegA, *pinw, *pxpw, *poutw, *plmw, *pembw;
    cudaGetSymbolAddress((void**)&ph,     g_h);
    cudaGetSymbolAddress((void**)&pxn,    g_xn);
    cudaGetSymbolAddress((void**)&pxz,    g_xz);
    cudaGetSymbolAddress((void**)&pxct,   g_xct);
    cudaGetSymbolAddress((void**)&pdbc,   g_dbc);
    cudaGetSymbolAddress((void**)&pdelta, g_delta);
    cudaGetSymbolAddress((void**)&pys,    g_ys);
    cudaGetSymbolAddress((void**)&plog,   g_logit);
    cudaGetSymbolAddress((void**)&pnrm,   g_nrm);
    cudaGetSymbolAddress((void**)&pt,     g_t);
    cudaGetSymbolAddress((void**)&pdtw,   g_dtw);
    cudaGetSymbolAddress((void**)&pnegA,  g_negA);
    cudaGetSymbolAddress((void**)&pinw,   g_inw);
    cudaGetSymbolAddress((void**)&pxpw,   g_xpw);
    cudaGetSymbolAddress((void**)&poutw,  g_outw);
    cudaGetSymbolAddress((void**)&plmw,   g_lmw);
    cudaGetSymbolAddress((void**)&pembw,  g_embw);

    // launch indices 0..5 chosen so ncu (-s 5 -c 1) profiles the big in_proj GEMM
    k_transpose_in<<<(NR*DM + 255)/256, 256>>>(x);                       // 0
    k_cvt<<<(N_INW + 255)/256, 256>>>(in_w, pinw, N_INW);                // 1
    k_cvt<<<(N_OUTW + 255)/256, 256>>>(out_w, poutw, N_OUTW);            // 2
    k_cvt<<<(N_XPW + 255)/256, 256>>>(xp_w, pxpw, N_XPW);                // 3

    for (int l = 0; l < 2; l++){
        k_rmsnorm<<<NR, 256>>>(norm_w + l*DM);                           // 4
        // xz = xn @ in_w^T   (1536 x 6200, K=1550)
        k_mma<4><<<dim3(49, 12), 256, SMEM_MMA4>>>(                      // 5 <- profiled
            pxn, DM, pinw + (size_t)l*2*ED*DM, DM, pxz, 2*ED, NR, 2*ED, DM, 0, nullptr);
        k_conv_silu<<<dim3((ED+255)/256, BSZ), 256>>>(conv_w + (size_t)l*ED*4, conv_b + l*ED);
        if (l == 0){
            k_padw<<<(2*ED*DTWP + 255)/256, 256>>>(dt_w);
            k_negA<<<(2*ED*DS + 255)/256, 256>>>(A_log);
        }
        // dbc = xct @ xp_w^T  (1536 x 129, K=3100); round dt cols only
        k_mma<2><<<dim3(2, 24), 256, SMEM_MMA2>>>(
            pxct, ED, pxpw + (size_t)l*DBCN*ED, ED, pdbc, DBCP, NR, DBCN, ED, 3, nullptr);
        // delta = softplus(dt @ dtw^T + dt_b)  (1536 x 3100, K=104 padded w/ zeros)
        k_mma<4><<<dim3(25, 12), 256, SMEM_MMA4>>>(
            pdbc, DBCP, pdtw + (size_t)l*ED*DTWP, DTWP, pdelta, ED, NR, ED, DTWP, 2, dt_b + l*ED);
        // scan -> ys
        k_scan<<<dim3((ED+255)/256, BSZ), 256>>>(pnegA + (size_t)l*ED*DS, D_param + l*ED);
        // h += ys @ out_w^T  (1536 x 1550, K=3100)
        k_mma<4><<<dim3(13, 12), 256, SMEM_MMA4>>>(
            pys, ED, poutw + (size_t)l*DM*ED, ED, ph, DM, NR, DM, ED, 1, nullptr);
    }

    k_rmsnorm<<<NR, 256>>>(normf_w);
    k_cvt<<<(N_LMW + 255)/256, 256>>>(lm_w, plmw, N_LMW);
    // logits = xn @ lm_w^T  (1536 x 128, K=1550)
    k_mma<2><<<dim3(1, 24), 256, SMEM_MMA2>>>(
        pxn, DM, plmw, DM, plog, VOC, NR, VOC, DM, 0, nullptr);
    k_red1<<<192, 256>>>();
    k_red2<<<1, 256>>>();
    k_nrm<<<(NR*VOC + 255)/256, 256>>>();
    k_cvt<<<(N_EMBW + 255)/256, 256>>>(emb_w, pembw, N_EMBW);
    // t = nrm @ emb_w^T  (1536 x 256, K=128)
    k_mma<2><<<dim3(2, 24), 256, SMEM_MMA2>>>(
        pnrm, VOC, pembw, VOC, pt, OE, NR, OE, VOC, 0, nullptr);
    k_wesum<<<1, 256>>>(emb_w);
    k_final<<<(BSZ*5*SEQ*OE + 255)/256, 256>>>(bn_w, bn_b, emb_b, out);
}

// round 5
// speedup vs baseline: 2.5955x; 1.4561x over previous
#include <cuda_runtime.h>
#include <cuda_fp16.h>
#include <math.h>
#include <stdint.h>

// ---------------- problem constants ----------------
#define BSZ   512
#define SEQ   3
#define DM    1550
#define DMP   1568          // DM padded to x32
#define DS    16
#define ED    3100
#define EDP   3104          // ED padded to x32
#define DTR   97
#define DTKP  128           // dt GEMM K padded to x32
#define DBCN  129
#define DBCP  132           // fp32 dbc ldc
#define VOC   128
#define NR    (BSZ*SEQ)
#define OE    256
#define EPSF  1e-5f

#define SROW  40            // smem row stride in halves (80B): banks (20g+tg)%32 distinct

// ---------------- fp32 scratch ----------------
__device__ __align__(256) float g_h    [NR*DM];
__device__ __align__(256) float g_xz   [NR*2*ED];
__device__ __align__(256) float g_xc   [NR*ED];
__device__ __align__(256) float g_dbc  [NR*DBCP];
__device__ __align__(256) float g_delta[NR*ED];
__device__ __align__(256) float g_negA [2*ED*DS];
__device__ __align__(256) float g_logit[NR*VOC];
__device__ __align__(256) float g_t    [NR*OE];
__device__ float g_part [384];
__device__ float g_stats[2];
__device__ float g_wesum[OE];

// ---------------- fp16 GEMM operand scratch (zero-init pads) ----------------
__device__ __align__(256) __half h_xn  [NR*DMP];
__device__ __align__(256) __half h_inw [2*2*ED*DMP];
__device__ __align__(256) __half h_xct [NR*EDP];
__device__ __align__(256) __half h_xpw [2*DBCN*EDP];
__device__ __align__(256) __half h_dbc [NR*DTKP];
__device__ __align__(256) __half h_dtw [2*ED*DTKP];
__device__ __align__(256) __half h_ys  [NR*EDP];
__device__ __align__(256) __half h_outw[2*DM*EDP];
__device__ __align__(256) __half h_lmw [VOC*DMP];
__device__ __align__(256) __half h_nrm [NR*VOC];
__device__ __align__(256) __half h_embw[OE*VOC];

__device__ __forceinline__ float siluf(float v){ return v / (1.f + expf(-v)); }

__device__ __forceinline__ void mma_f16(float c[4],
    uint32_t a0, uint32_t a1, uint32_t a2, uint32_t a3,
    uint32_t b0, uint32_t b1)
{
    asm volatile(
        "mma.sync.aligned.m16n8k16.row.col.f32.f16.f16.f32 "
        "{%0,%1,%2,%3}, {%4,%5,%6,%7}, {%8,%9}, {%0,%1,%2,%3};"
        : "+f"(c[0]), "+f"(c[1]), "+f"(c[2]), "+f"(c[3])
        : "r"(a0), "r"(a1), "r"(a2), "r"(a3), "r"(b0), "r"(b1));
}

__device__ __forceinline__ void cpa16(uint32_t sdst, const __half* gsrc, int nbytes){
    asm volatile("cp.async.cg.shared.global [%0], [%1], 16, %2;"
                 :: "r"(sdst), "l"(gsrc), "r"(nbytes));
}

// ---------------- FP16 tensor-core GEMM, cp.async double-buffered ----------------
// C[M,N] (op)= A[M,K] * B[N,K]^T. fp16 operands, fp32 accum.
// MT=4 -> BM=128 ; MT=2 -> BM=64. BN=128, BK=32.
// Requirements: M % BM == 0; K % 32 == 0; lda, ldb % 8 == 0 (16B rows).
// mode 0: C = acc ; 1: C += acc ; 2: C = softplus(acc + bias[n]) ;
// mode 3: C = acc AND Ch[r*ldch+c] = half(acc) for c < DTR.
template<int MT>
__global__ void __launch_bounds__(256, 2) k_hmma(
    const __half* __restrict__ A, int lda,
    const __half* __restrict__ B, int ldb,
    float* __restrict__ C, int ldc,
    int M, int N, int K,
    int mode, const float* __restrict__ bias,
    __half* __restrict__ Ch, int ldch)
{
    constexpr int BM = MT*32;
    extern __shared__ __half smh[];
    __half* As = smh;                    // [2][BM][SROW]
    __half* Bs = smh + 2*BM*SROW;        // [2][128][SROW]

    const int tid  = threadIdx.x;
    const int wid  = tid >> 5, lane = tid & 31;
    const int g    = lane >> 2, tg = lane & 3;
    const int wm   = (wid >> 2) * (MT*16);
    const int wn   = (wid & 3) * 32;
    const int bm   = blockIdx.y * BM;
    const int bn   = blockIdx.x * 128;

    const int arow = tid >> 2;           // 0..63
    const int acol = (tid & 3) * 8;      // half offset of 16B slot

    const uint32_t sA = (uint32_t)__cvta_generic_to_shared(As);
    const uint32_t sB = (uint32_t)__cvta_generic_to_shared(Bs);

    float acc[MT][4][4];
    #pragma unroll
    for (int mt = 0; mt < MT; mt++)
        #pragma unroll
        for (int nt = 0; nt < 4; nt++)
            #pragma unroll
            for (int i = 0; i < 4; i++) acc[mt][nt][i] = 0.f;

    const int nch = K >> 5;

    auto issue = [&](int c){
        const int gk = c*32 + acol;
        const int s  = c & 1;
        uint32_t da = sA + (uint32_t)(s*BM*SROW + arow*SROW + acol)*2u;
        #pragma unroll
        for (int p = 0; p < BM/64; p++)
            cpa16(da + (uint32_t)(p*64*SROW*2),
                  A + (size_t)(bm + arow + p*64)*lda + gk, 16);
        uint32_t db = sB + (uint32_t)(s*128*SROW + arow*SROW + acol)*2u;
        #pragma unroll
        for (int p = 0; p < 2; p++){
            int gn = bn + arow + p*64;
            cpa16(db + (uint32_t)(p*64*SROW*2),
                  B + (size_t)(gn < N ? gn : 0)*ldb + gk, (gn < N) ? 16 : 0);
        }
        asm volatile("cp.async.commit_group;");
    };

    issue(0);
    for (int c = 0; c < nch; c++){
        if (c + 1 < nch){
            issue(c + 1);
            asm volatile("cp.async.wait_group 1;");
        } else {
            asm volatile("cp.async.wait_group 0;");
        }
        __syncthreads();

        const __half* Ab = As + (c & 1)*BM*SROW;
        const __half* Bb = Bs + (c & 1)*128*SROW;
        #pragma unroll
        for (int kst = 0; kst < 2; kst++){
            const int ko = kst*16 + 2*tg;
            uint32_t af[MT][4], bf[4][2];
            #pragma unroll
            for (int mt = 0; mt < MT; mt++){
                const __half* pa = Ab + (wm + mt*16 + g)*SROW + ko;
                af[mt][0] = *(const uint32_t*)(pa);
                af[mt][1] = *(const uint32_t*)(pa + 8*SROW);
                af[mt][2] = *(const uint32_t*)(pa + 8);
                af[mt][3] = *(const uint32_t*)(pa + 8*SROW + 8);
            }
            #pragma unroll
            for (int nt = 0; nt < 4; nt++){
                const __half* pb = Bb + (wn + nt*8 + g)*SROW + ko;
                bf[nt][0] = *(const uint32_t*)(pb);
                bf[nt][1] = *(const uint32_t*)(pb + 8);
            }
            #pragma unroll
            for (int mt = 0; mt < MT; mt++)
                #pragma unroll
                for (int nt = 0; nt < 4; nt++)
                    mma_f16(acc[mt][nt], af[mt][0], af[mt][1], af[mt][2], af[mt][3],
                            bf[nt][0], bf[nt][1]);
        }
        __syncthreads();
    }

    // ---- epilogue ----
    #pragma unroll
    for (int mt = 0; mt < MT; mt++){
        int r0 = bm + wm + mt*16 + g;
        #pragma unroll
        for (int nt = 0; nt < 4; nt++){
            int cl = bn + wn + nt*8 + 2*tg;
            #pragma unroll
            for (int i = 0; i < 4; i++){
                int rr = r0 + (i >> 1)*8;
                int cc = cl + (i & 1);
                if (cc >= N) continue;
                float v = acc[mt][nt][i];
                size_t idx = (size_t)rr*ldc + cc;
                if (mode == 1){
                    v += C[idx];
                } else if (mode == 2){
                    float xv = v + bias[cc];
                    v = fmaxf(xv, 0.f) + log1pf(expf(-fabsf(xv)));
                } else if (mode == 3){
                    if (cc < DTR) Ch[(size_t)rr*ldch + cc] = __float2half(v);
                }
                C[idx] = v;
            }
        }
    }
}

#define SMEMH4 (2*(128+128)*SROW*sizeof(__half))   // 40960
#define SMEMH2 (2*(64 +128)*SROW*sizeof(__half))   // 30720

// ---------------- fp32 -> padded fp16 weight conversion ----------------
__global__ void k_cvtw(const float* __restrict__ src, __half* __restrict__ dst,
                       int K, int KP, int n){
    int i = blockIdx.x*blockDim.x + threadIdx.x;
    if (i < n) dst[(size_t)(i/K)*KP + (i%K)] = __float2half(src[i]);
}

// ---------------- input transpose ----------------
__global__ void k_transpose_in(const float* __restrict__ x){
    int i = blockIdx.x*blockDim.x + threadIdx.x;
    if (i >= NR*DM) return;
    int n = i / DM, d = i % DM;
    int c = d / 25, r = d % 25, f = r / 5, e = r % 5;
    g_h[i] = x[((n*5 + f)*62 + c)*5 + e];
}

// ---------------- rmsnorm: g_h -> h_xn (fp16, padded) ----------------
__global__ void k_rmsnorm(const float* __restrict__ w){
    __shared__ float sh[33];
    int n = blockIdx.x;
    const float* row = g_h + (size_t)n*DM;
    float ss = 0.f;
    for (int d = threadIdx.x; d < DM; d += blockDim.x){ float v = row[d]; ss += v*v; }
    for (int o = 16; o; o >>= 1) ss += __shfl_down_sync(0xffffffffu, ss, o);
    if ((threadIdx.x & 31) == 0) sh[threadIdx.x >> 5] = ss;
    __syncthreads();
    if (threadIdx.x < 32){
        float v = (threadIdx.x < (int)(blockDim.x >> 5)) ? sh[threadIdx.x] : 0.f;
        for (int o = 16; o; o >>= 1) v += __shfl_down_sync(0xffffffffu, v, o);
        if (threadIdx.x == 0) sh[32] = rsqrtf(v / (float)DM + EPSF);
    }
    __syncthreads();
    float sc = sh[32];
    for (int d = threadIdx.x; d < DM; d += blockDim.x)
        h_xn[(size_t)n*DMP + d] = __float2half(row[d] * sc * w[d]);
}

// ---------------- depthwise causal conv + silu; fp32 exact + fp16 copy ----------------
__global__ void k_conv_silu(const float* __restrict__ cw, const float* __restrict__ cb){
    int e = blockIdx.x*blockDim.x + threadIdx.x;
    int b = blockIdx.y;
    if (e >= ED) return;
    size_t r0 = (size_t)(b*SEQ + 0)*(2*ED);
    size_t r1 = (size_t)(b*SEQ + 1)*(2*ED);
    size_t r2 = (size_t)(b*SEQ + 2)*(2*ED);
    float x0 = g_xz[r0 + e], x1 = g_xz[r1 + e], x2 = g_xz[r2 + e];
    float w1 = cw[e*4+1], w2 = cw[e*4+2], w3 = cw[e*4+3];
    float bb = cb[e];
    float y0 = siluf(bb + w3*x0);
    float y1 = siluf(bb + w2*x0 + w3*x1);
    float y2 = siluf(bb + w1*x0 + w2*x1 + w3*x2);
    g_xc[(size_t)(b*SEQ + 0)*ED + e] = y0;  h_xct[(size_t)(b*SEQ + 0)*EDP + e] = __float2half(y0);
    g_xc[(size_t)(b*SEQ + 1)*ED + e] = y1;  h_xct[(size_t)(b*SEQ + 1)*EDP + e] = __float2half(y1);
    g_xc[(size_t)(b*SEQ + 2)*ED + e] = y2;  h_xct[(size_t)(b*SEQ + 2)*EDP + e] = __float2half(y2);
}

// ---------------- negA (both layers) ----------------
__global__ void k_negA(const float* __restrict__ Alog){
    int i = blockIdx.x*blockDim.x + threadIdx.x;
    if (i < 2*ED*DS) g_negA[i] = -expf(Alog[i]);
}

// ---------------- fused SSM scan (S=3), + D*xc, * silu(z) -> h_ys fp16 ----------------
__global__ void k_scan(const float* __restrict__ nAbase, const float* __restrict__ Dp){
    __shared__ float sB[SEQ][DS], sC[SEQ][DS];
    int e = blockIdx.x*blockDim.x + threadIdx.x;
    int b = blockIdx.y;
    int t = threadIdx.x;
    if (t < SEQ*DS){
        int s = t / DS, n = t % DS;
        size_t base = (size_t)(b*SEQ + s)*DBCP + DTR;
        sB[s][n] = g_dbc[base + n];
        sC[s][n] = g_dbc[base + DS + n];
    }
    __syncthreads();
    if (e >= ED) return;

    float nA[DS], hst[DS];
    #pragma unroll
    for (int n = 0; n < DS; n++){ nA[n] = nAbase[e*DS + n]; hst[n] = 0.f; }
    float dpe = Dp[e];

    #pragma unroll
    for (int s = 0; s < SEQ; s++){
        size_t row = (size_t)(b*SEQ + s);
        float d   = g_delta[row*ED + e];
        float xcv = g_xc[row*ED + e];
        float dx  = d * xcv;
        float y = 0.f;
        #pragma unroll
        for (int n = 0; n < DS; n++){
            float dA = __expf(d * nA[n]);
            hst[n] = dA*hst[n] + dx*sB[s][n];
            y = fmaf(hst[n], sC[s][n], y);
        }
        y += dpe * xcv;
        float z = g_xz[row*(2*ED) + ED + e];
        h_ys[row*EDP + e] = __float2half(y * siluf(z));
    }
}

// ---------------- logits mean/var (deterministic 2-pass) ----------------
__global__ void k_red1(){
    __shared__ float s1[32], s2[32];
    int base = blockIdx.x * 1024;
    float s = 0.f, q = 0.f;
    for (int i = threadIdx.x; i < 1024; i += 256){
        float v = g_logit[base + i];
        s += v; q += v*v;
    }
    for (int o = 16; o; o >>= 1){
        s += __shfl_down_sync(0xffffffffu, s, o);
        q += __shfl_down_sync(0xffffffffu, q, o);
    }
    if ((threadIdx.x & 31) == 0){ s1[threadIdx.x>>5] = s; s2[threadIdx.x>>5] = q; }
    __syncthreads();
    if (threadIdx.x < 32){
        float a = (threadIdx.x < 8) ? s1[threadIdx.x] : 0.f;
        float c = (threadIdx.x < 8) ? s2[threadIdx.x] : 0.f;
        for (int o = 4; o; o >>= 1){
            a += __shfl_down_sync(0xffffffffu, a, o);
            c += __shfl_down_sync(0xffffffffu, c, o);
        }
        if (threadIdx.x == 0){ g_part[blockIdx.x*2] = a; g_part[blockIdx.x*2+1] = c; }
    }
}

__global__ void k_red2(){
    __shared__ float s1[32], s2[32];
    float s = 0.f, q = 0.f;
    for (int i = threadIdx.x; i < 192; i += 256){ s += g_part[i*2]; q += g_part[i*2+1]; }
    for (int o = 16; o; o >>= 1){
        s += __shfl_down_sync(0xffffffffu, s, o);
        q += __shfl_down_sync(0xffffffffu, q, o);
    }
    if ((threadIdx.x & 31) == 0){ s1[threadIdx.x>>5] = s; s2[threadIdx.x>>5] = q; }
    __syncthreads();
    if (threadIdx.x == 0){
        float a = 0.f, c = 0.f;
        for (int i = 0; i < 8; i++){ a += s1[i]; c += s2[i]; }
        const float T = (float)(NR*VOC);
        float mean = a / T;
        float var  = c / T - mean*mean;
        g_stats[0] = mean;
        g_stats[1] = rsqrtf(var + EPSF);
    }
}

__global__ void k_nrm(){
    int i = blockIdx.x*blockDim.x + threadIdx.x;
    if (i < NR*VOC) h_nrm[i] = __float2half((g_logit[i] - g_stats[0]) * g_stats[1]);
}

__global__ void k_wesum(const float* __restrict__ emb_w){
    int o = threadIdx.x;
    float s = 0.f;
    for (int v = 0; v < VOC; v++) s += emb_w[o*VOC + v];
    g_wesum[o] = s;
}

// ---------------- final expand over f ----------------
__global__ void k_final(const float* __restrict__ bnw, const float* __restrict__ bnb,
                        const float* __restrict__ embb, float* __restrict__ out){
    int i = blockIdx.x*blockDim.x + threadIdx.x;
    const int total = BSZ*5*SEQ*OE;
    if (i >= total) return;
    int o = i & 255;
    int s = (i >> 8) % SEQ;
    int f = (i / (OE*SEQ)) % 5;
    int b = i / (OE*SEQ*5);
    int n = b*SEQ + s;
    out[i] = bnw[f]*g_t[(size_t)n*OE + o] + bnb[f]*g_wesum[o] + embb[o];
}

// ---------------- launch ----------------
extern "C" void kernel_launch(void* const* d_in, const int* in_sizes, int n_in,
                              void* d_out, int out_size)
{
    const float* x        = (const float*)d_in[0];
    const float* in_w     = (const float*)d_in[1];
    const float* conv_w   = (const float*)d_in[2];
    const float* conv_b   = (const float*)d_in[3];
    const float* xp_w     = (const float*)d_in[4];
    const float* dt_w     = (const float*)d_in[5];
    const float* dt_b     = (const float*)d_in[6];
    const float* A_log    = (const float*)d_in[7];
    const float* D_param  = (const float*)d_in[8];
    const float* out_w    = (const float*)d_in[9];
    const float* norm_w   = (const float*)d_in[10];
    const float* normf_w  = (const float*)d_in[11];
    const float* lm_w     = (const float*)d_in[12];
    const float* bn_w     = (const float*)d_in[13];
    const float* bn_b     = (const float*)d_in[14];
    const float* emb_w    = (const float*)d_in[15];
    const float* emb_b    = (const float*)d_in[16];
    float* out = (float*)d_out;

    float *pxz, *pxc, *pdbc, *pdelta, *ph, *plog, *pt, *pnegA;
    __half *qxn, *qinw, *qxct, *qxpw, *qdbc, *qdtw, *qys, *qoutw, *qlmw, *qnrm, *qembw;
    cudaGetSymbolAddress((void**)&ph,     g_h);
    cudaGetSymbolAddress((void**)&pxz,    g_xz);
    cudaGetSymbolAddress((void**)&pxc,    g_xc);
    cudaGetSymbolAddress((void**)&pdbc,   g_dbc);
    cudaGetSymbolAddress((void**)&pdelta, g_delta);
    cudaGetSymbolAddress((void**)&plog,   g_logit);
    cudaGetSymbolAddress((void**)&pt,     g_t);
    cudaGetSymbolAddress((void**)&pnegA,  g_negA);
    cudaGetSymbolAddress((void**)&qxn,    h_xn);
    cudaGetSymbolAddress((void**)&qinw,   h_inw);
    cudaGetSymbolAddress((void**)&qxct,   h_xct);
    cudaGetSymbolAddress((void**)&qxpw,   h_xpw);
    cudaGetSymbolAddress((void**)&qdbc,   h_dbc);
    cudaGetSymbolAddress((void**)&qdtw,   h_dtw);
    cudaGetSymbolAddress((void**)&qys,    h_ys);
    cudaGetSymbolAddress((void**)&qoutw,  h_outw);
    cudaGetSymbolAddress((void**)&qlmw,   h_lmw);
    cudaGetSymbolAddress((void**)&qnrm,   h_nrm);
    cudaGetSymbolAddress((void**)&qembw,  h_embw);

    const int NIN = 2*2*ED*DM, NOUT = 2*DM*ED, NXP = 2*DBCN*ED, NDT = 2*ED*DTR;

    // launches 0..3: profiled launch (index 3) = big in_proj GEMM
    k_transpose_in<<<(NR*DM + 255)/256, 256>>>(x);                          // 0
    k_cvtw<<<(NIN + 255)/256, 256>>>(in_w, qinw, DM, DMP, NIN);             // 1
    k_rmsnorm<<<NR, 256>>>(norm_w);                                         // 2
    k_hmma<4><<<dim3(49, 12), 256, SMEMH4>>>(                               // 3 <- profiled
        qxn, DMP, qinw, DMP, pxz, 2*ED, NR, 2*ED, DMP, 0, nullptr, nullptr, 0);

    // remaining weight conversions (needed from first dbc GEMM onward)
    k_cvtw<<<(NOUT + 255)/256, 256>>>(out_w, qoutw, ED, EDP, NOUT);
    k_cvtw<<<(NXP + 255)/256, 256>>>(xp_w, qxpw, ED, EDP, NXP);
    k_cvtw<<<(NDT + 255)/256, 256>>>(dt_w, qdtw, DTR, DTKP, NDT);
    k_negA<<<(2*ED*DS + 255)/256, 256>>>(A_log);

    for (int l = 0; l < 2; l++){
        if (l == 1){
            k_rmsnorm<<<NR, 256>>>(norm_w + DM);
            k_hmma<4><<<dim3(49, 12), 256, SMEMH4>>>(
                qxn, DMP, qinw + (size_t)2*ED*DMP, DMP, pxz, 2*ED, NR, 2*ED, DMP, 0, nullptr, nullptr, 0);
        }
        k_conv_silu<<<dim3((ED+255)/256, BSZ), 256>>>(conv_w + (size_t)l*ED*4, conv_b + l*ED);
        // dbc = xct @ xp_w^T  (1536 x 129, K=3104); fp32 out + fp16 dt cols
        k_hmma<2><<<dim3(2, 24), 256, SMEMH2>>>(
            qxct, EDP, qxpw + (size_t)l*DBCN*EDP, EDP, pdbc, DBCP, NR, DBCN, EDP, 3, nullptr, qdbc, DTKP);
        // delta = softplus(dt @ dtw^T + dt_b)  (1536 x 3100, K=128)
        k_hmma<4><<<dim3(25, 12), 256, SMEMH4>>>(
            qdbc, DTKP, qdtw + (size_t)l*ED*DTKP, DTKP, pdelta, ED, NR, ED, DTKP, 2, dt_b + l*ED, nullptr, 0);
        // scan -> h_ys
        k_scan<<<dim3((ED+255)/256, BSZ), 256>>>(pnegA + (size_t)l*ED*DS, D_param + l*ED);
        // h += ys @ out_w^T  (1536 x 1550, K=3104)
        k_hmma<4><<<dim3(13, 12), 256, SMEMH4>>>(
            qys, EDP, qoutw + (size_t)l*DM*EDP, EDP, ph, DM, NR, DM, EDP, 1, nullptr, nullptr, 0);
    }

    k_rmsnorm<<<NR, 256>>>(normf_w);
    k_cvtw<<<(VOC*DM + 255)/256, 256>>>(lm_w, qlmw, DM, DMP, VOC*DM);
    // logits = xn @ lm_w^T  (1536 x 128, K=1568)
    k_hmma<2><<<dim3(1, 24), 256, SMEMH2>>>(
        qxn, DMP, qlmw, DMP, plog, VOC, NR, VOC, DMP, 0, nullptr, nullptr, 0);
    k_red1<<<192, 256>>>();
    k_red2<<<1, 256>>>();
    k_nrm<<<(NR*VOC + 255)/256, 256>>>();
    k_cvtw<<<(OE*VOC + 255)/256, 256>>>(emb_w, qembw, VOC, VOC, OE*VOC);
    // t = nrm @ emb_w^T  (1536 x 256, K=128)
    k_hmma<2><<<dim3(2, 24), 256, SMEMH2>>>(
        qnrm, VOC, qembw, VOC, pt, OE, NR, OE, VOC, 0, nullptr, nullptr, 0);
    k_wesum<<<1, 256>>>(emb_w);
    k_final<<<(BSZ*5*SEQ*OE + 255)/256, 256>>>(bn_w, bn_b, emb_b, out);
}

// round 6
// speedup vs baseline: 3.0035x; 1.1572x over previous
#include <cuda_runtime.h>
#include <cuda_fp16.h>
#include <math.h>
#include <stdint.h>

// ---------------- problem constants ----------------
#define BSZ   512
#define SEQ   3
#define DM    1550
#define DMP   1600          // DM padded to x64
#define DS    16
#define ED    3100
#define EDP   3136          // ED padded to x64
#define DTR   97
#define DTKP  128           // dt GEMM K padded
#define DBCN  129
#define DBCP  132           // fp32 dbc ldc
#define VOC   128
#define NR    (BSZ*SEQ)
#define OE    256
#define EPSF  1e-5f

#define SROW  72            // smem row stride in halves (BK=64 + 8 pad)

// ---------------- fp32 scratch ----------------
__device__ __align__(256) float g_h    [NR*DM];
__device__ __align__(256) float g_xz   [NR*2*ED];
__device__ __align__(256) float g_xc   [NR*ED];
__device__ __align__(256) float g_dbc  [NR*DBCP];
__device__ __align__(256) float g_delta[NR*ED];
__device__ __align__(256) float g_negA [2*ED*DS];
__device__ __align__(256) float g_logit[NR*VOC];
__device__ __align__(256) float g_t    [NR*OE];
__device__ float g_part [384];
__device__ float g_stats[2];
__device__ float g_wesum[OE];

// ---------------- fp16 GEMM operand scratch (zero-init pads) ----------------
__device__ __align__(256) __half h_xn  [NR*DMP];
__device__ __align__(256) __half h_inw [2*2*ED*DMP];
__device__ __align__(256) __half h_xct [NR*EDP];
__device__ __align__(256) __half h_xpw [2*DBCN*EDP];
__device__ __align__(256) __half h_dbc [NR*DTKP];
__device__ __align__(256) __half h_dtw [2*ED*DTKP];
__device__ __align__(256) __half h_ys  [NR*EDP];
__device__ __align__(256) __half h_outw[2*DM*EDP];
__device__ __align__(256) __half h_lmw [VOC*DMP];
__device__ __align__(256) __half h_nrm [NR*VOC];
__device__ __align__(256) __half h_embw[OE*VOC];

__device__ __forceinline__ float siluf(float v){ return v / (1.f + expf(-v)); }

__device__ __forceinline__ void mma_f16(float c[4],
    uint32_t a0, uint32_t a1, uint32_t a2, uint32_t a3,
    uint32_t b0, uint32_t b1)
{
    asm volatile(
        "mma.sync.aligned.m16n8k16.row.col.f32.f16.f16.f32 "
        "{%0,%1,%2,%3}, {%4,%5,%6,%7}, {%8,%9}, {%0,%1,%2,%3};"
        : "+f"(c[0]), "+f"(c[1]), "+f"(c[2]), "+f"(c[3])
        : "r"(a0), "r"(a1), "r"(a2), "r"(a3), "r"(b0), "r"(b1));
}

__device__ __forceinline__ void cpa16(uint32_t sdst, const __half* gsrc, int nbytes){
    asm volatile("cp.async.cg.shared.global [%0], [%1], 16, %2;"
                 :: "r"(sdst), "l"(gsrc), "r"(nbytes));
}

// ---------------- FP16 tensor-core GEMM, BK=64, cp.async double-buffered ----------------
// C[M,N] (op)= A[M,K] * B[N,K]^T. fp16 operands, fp32 accum.
// MT=4 -> BM=128 ; MT=2 -> BM=64. BN=128, BK=64.
// Requirements: M % BM == 0; K % 64 == 0; lda, ldb % 8 == 0.
// mode 0: C = acc ; 1: C += acc ; 2: C = softplus(acc + bias[n]) ;
// mode 3: C = acc AND Ch[r*ldch+c] = half(acc) for c < DTR.
template<int MT>
__global__ void __launch_bounds__(256, 2) k_hmma(
    const __half* __restrict__ A, int lda,
    const __half* __restrict__ B, int ldb,
    float* __restrict__ C, int ldc,
    int M, int N, int K,
    int mode, const float* __restrict__ bias,
    __half* __restrict__ Ch, int ldch)
{
    constexpr int BM = MT*32;
    extern __shared__ __half smh[];
    __half* As = smh;                    // [2][BM][SROW]
    __half* Bs = smh + 2*BM*SROW;        // [2][128][SROW]

    const int tid  = threadIdx.x;
    const int wid  = tid >> 5, lane = tid & 31;
    const int g    = lane >> 2, tg = lane & 3;
    const int wm   = (wid >> 2) * (MT*16);
    const int wn   = (wid & 3) * 32;
    const int bm   = blockIdx.y * BM;
    const int bn   = blockIdx.x * 128;

    const int lrow = tid >> 3;           // 0..31
    const int lcol = (tid & 7) * 8;      // half offset of 16B slot in 64-wide row

    const uint32_t sA = (uint32_t)__cvta_generic_to_shared(As);
    const uint32_t sB = (uint32_t)__cvta_generic_to_shared(Bs);

    float acc[MT][4][4];
    #pragma unroll
    for (int mt = 0; mt < MT; mt++)
        #pragma unroll
        for (int nt = 0; nt < 4; nt++)
            #pragma unroll
            for (int i = 0; i < 4; i++) acc[mt][nt][i] = 0.f;

    const int nch = K >> 6;

    auto issue = [&](int c){
        const int gk = c*64 + lcol;
        const int s  = c & 1;
        uint32_t da = sA + (uint32_t)(s*BM*SROW + lrow*SROW + lcol)*2u;
        #pragma unroll
        for (int p = 0; p < BM/32; p++)
            cpa16(da + (uint32_t)(p*32*SROW*2),
                  A + (size_t)(bm + lrow + p*32)*lda + gk, 16);
        uint32_t db = sB + (uint32_t)(s*128*SROW + lrow*SROW + lcol)*2u;
        #pragma unroll
        for (int p = 0; p < 4; p++){
            int gn = bn + lrow + p*32;
            cpa16(db + (uint32_t)(p*32*SROW*2),
                  B + (size_t)(gn < N ? gn : 0)*ldb + gk, (gn < N) ? 16 : 0);
        }
        asm volatile("cp.async.commit_group;");
    };

    issue(0);
    for (int c = 0; c < nch; c++){
        if (c + 1 < nch){
            issue(c + 1);
            asm volatile("cp.async.wait_group 1;");
        } else {
            asm volatile("cp.async.wait_group 0;");
        }
        __syncthreads();

        const __half* Ab = As + (c & 1)*BM*SROW;
        const __half* Bb = Bs + (c & 1)*128*SROW;
        #pragma unroll
        for (int kst = 0; kst < 4; kst++){
            const int ko = kst*16 + 2*tg;
            uint32_t af[MT][4], bf[4][2];
            #pragma unroll
            for (int mt = 0; mt < MT; mt++){
                const __half* pa = Ab + (wm + mt*16 + g)*SROW + ko;
                af[mt][0] = *(const uint32_t*)(pa);
                af[mt][1] = *(const uint32_t*)(pa + 8*SROW);
                af[mt][2] = *(const uint32_t*)(pa + 8);
                af[mt][3] = *(const uint32_t*)(pa + 8*SROW + 8);
            }
            #pragma unroll
            for (int nt = 0; nt < 4; nt++){
                const __half* pb = Bb + (wn + nt*8 + g)*SROW + ko;
                bf[nt][0] = *(const uint32_t*)(pb);
                bf[nt][1] = *(const uint32_t*)(pb + 8);
            }
            #pragma unroll
            for (int mt = 0; mt < MT; mt++)
                #pragma unroll
                for (int nt = 0; nt < 4; nt++)
                    mma_f16(acc[mt][nt], af[mt][0], af[mt][1], af[mt][2], af[mt][3],
                            bf[nt][0], bf[nt][1]);
        }
        __syncthreads();
    }

    // ---- epilogue ----
    #pragma unroll
    for (int mt = 0; mt < MT; mt++){
        int r0 = bm + wm + mt*16 + g;
        #pragma unroll
        for (int nt = 0; nt < 4; nt++){
            int cl = bn + wn + nt*8 + 2*tg;
            #pragma unroll
            for (int i = 0; i < 4; i++){
                int rr = r0 + (i >> 1)*8;
                int cc = cl + (i & 1);
                if (cc >= N) continue;
                float v = acc[mt][nt][i];
                size_t idx = (size_t)rr*ldc + cc;
                if (mode == 1){
                    v += C[idx];
                } else if (mode == 2){
                    float xv = v + bias[cc];
                    v = fmaxf(xv, 0.f) + log1pf(expf(-fabsf(xv)));
                } else if (mode == 3){
                    if (cc < DTR) Ch[(size_t)rr*ldch + cc] = __float2half(v);
                }
                C[idx] = v;
            }
        }
    }
}

#define SMEMH4 (2*(128+128)*SROW*sizeof(__half))   // 73728
#define SMEMH2 (2*(64 +128)*SROW*sizeof(__half))   // 55296

// ---------------- vectorized fp32 -> padded fp16 (one block per row, K even) ----------------
__global__ void k_cvt2(const float* __restrict__ src, __half* __restrict__ dst,
                       int K, int KP){
    int r = blockIdx.x;
    const float2* s = (const float2*)(src + (size_t)r*K);
    __half* d = dst + (size_t)r*KP;
    const int n2 = K >> 1;
    for (int i = threadIdx.x; i < n2; i += blockDim.x){
        float2 v = s[i];
        *(__half2*)(d + 2*i) = __floats2half2_rn(v.x, v.y);
    }
}

// scalar pad conversion for odd-K dt_w
__global__ void k_cvtw(const float* __restrict__ src, __half* __restrict__ dst,
                       int K, int KP, int n){
    int i = blockIdx.x*blockDim.x + threadIdx.x;
    if (i < n) dst[(size_t)(i/K)*KP + (i%K)] = __float2half(src[i]);
}

// ---------------- input transpose ----------------
__global__ void k_transpose_in(const float* __restrict__ x){
    int i = blockIdx.x*blockDim.x + threadIdx.x;
    if (i >= NR*DM) return;
    int n = i / DM, d = i % DM;
    int c = d / 25, r = d % 25, f = r / 5, e = r % 5;
    g_h[i] = x[((n*5 + f)*62 + c)*5 + e];
}

// ---------------- rmsnorm: g_h -> h_xn (fp16, padded) ----------------
__global__ void k_rmsnorm(const float* __restrict__ w){
    __shared__ float sh[33];
    int n = blockIdx.x;
    const float* row = g_h + (size_t)n*DM;
    float ss = 0.f;
    for (int d = threadIdx.x; d < DM; d += blockDim.x){ float v = row[d]; ss += v*v; }
    for (int o = 16; o; o >>= 1) ss += __shfl_down_sync(0xffffffffu, ss, o);
    if ((threadIdx.x & 31) == 0) sh[threadIdx.x >> 5] = ss;
    __syncthreads();
    if (threadIdx.x < 32){
        float v = (threadIdx.x < (int)(blockDim.x >> 5)) ? sh[threadIdx.x] : 0.f;
        for (int o = 16; o; o >>= 1) v += __shfl_down_sync(0xffffffffu, v, o);
        if (threadIdx.x == 0) sh[32] = rsqrtf(v / (float)DM + EPSF);
    }
    __syncthreads();
    float sc = sh[32];
    for (int d = threadIdx.x; d < DM; d += blockDim.x)
        h_xn[(size_t)n*DMP + d] = __float2half(row[d] * sc * w[d]);
}

// ---------------- depthwise causal conv + silu; fp32 exact + fp16 copy ----------------
__global__ void k_conv_silu(const float* __restrict__ cw, const float* __restrict__ cb){
    int e = blockIdx.x*blockDim.x + threadIdx.x;
    int b = blockIdx.y;
    if (e >= ED) return;
    size_t r0 = (size_t)(b*SEQ + 0)*(2*ED);
    size_t r1 = (size_t)(b*SEQ + 1)*(2*ED);
    size_t r2 = (size_t)(b*SEQ + 2)*(2*ED);
    float x0 = g_xz[r0 + e], x1 = g_xz[r1 + e], x2 = g_xz[r2 + e];
    float w1 = cw[e*4+1], w2 = cw[e*4+2], w3 = cw[e*4+3];
    float bb = cb[e];
    float y0 = siluf(bb + w3*x0);
    float y1 = siluf(bb + w2*x0 + w3*x1);
    float y2 = siluf(bb + w1*x0 + w2*x1 + w3*x2);
    g_xc[(size_t)(b*SEQ + 0)*ED + e] = y0;  h_xct[(size_t)(b*SEQ + 0)*EDP + e] = __float2half(y0);
    g_xc[(size_t)(b*SEQ + 1)*ED + e] = y1;  h_xct[(size_t)(b*SEQ + 1)*EDP + e] = __float2half(y1);
    g_xc[(size_t)(b*SEQ + 2)*ED + e] = y2;  h_xct[(size_t)(b*SEQ + 2)*EDP + e] = __float2half(y2);
}

// ---------------- negA (both layers) ----------------
__global__ void k_negA(const float* __restrict__ Alog){
    int i = blockIdx.x*blockDim.x + threadIdx.x;
    if (i < 2*ED*DS) g_negA[i] = -expf(Alog[i]);
}

// ---------------- fused SSM scan (S=3), + D*xc, * silu(z) -> h_ys fp16 ----------------
__global__ void k_scan(const float* __restrict__ nAbase, const float* __restrict__ Dp){
    __shared__ float sB[SEQ][DS], sC[SEQ][DS];
    int e = blockIdx.x*blockDim.x + threadIdx.x;
    int b = blockIdx.y;
    int t = threadIdx.x;
    if (t < SEQ*DS){
        int s = t / DS, n = t % DS;
        size_t base = (size_t)(b*SEQ + s)*DBCP + DTR;
        sB[s][n] = g_dbc[base + n];
        sC[s][n] = g_dbc[base + DS + n];
    }
    __syncthreads();
    if (e >= ED) return;

    float nA[DS], hst[DS];
    #pragma unroll
    for (int n = 0; n < DS; n++){ nA[n] = nAbase[e*DS + n]; hst[n] = 0.f; }
    float dpe = Dp[e];

    #pragma unroll
    for (int s = 0; s < SEQ; s++){
        size_t row = (size_t)(b*SEQ + s);
        float d   = g_delta[row*ED + e];
        float xcv = g_xc[row*ED + e];
        float dx  = d * xcv;
        float y = 0.f;
        #pragma unroll
        for (int n = 0; n < DS; n++){
            float dA = __expf(d * nA[n]);
            hst[n] = dA*hst[n] + dx*sB[s][n];
            y = fmaf(hst[n], sC[s][n], y);
        }
        y += dpe * xcv;
        float z = g_xz[row*(2*ED) + ED + e];
        h_ys[row*EDP + e] = __float2half(y * siluf(z));
    }
}

// ---------------- logits mean/var (deterministic 2-pass) ----------------
__global__ void k_red1(){
    __shared__ float s1[32], s2[32];
    int base = blockIdx.x * 1024;
    float s = 0.f, q = 0.f;
    for (int i = threadIdx.x; i < 1024; i += 256){
        float v = g_logit[base + i];
        s += v; q += v*v;
    }
    for (int o = 16; o; o >>= 1){
        s += __shfl_down_sync(0xffffffffu, s, o);
        q += __shfl_down_sync(0xffffffffu, q, o);
    }
    if ((threadIdx.x & 31) == 0){ s1[threadIdx.x>>5] = s; s2[threadIdx.x>>5] = q; }
    __syncthreads();
    if (threadIdx.x < 32){
        float a = (threadIdx.x < 8) ? s1[threadIdx.x] : 0.f;
        float c = (threadIdx.x < 8) ? s2[threadIdx.x] : 0.f;
        for (int o = 4; o; o >>= 1){
            a += __shfl_down_sync(0xffffffffu, a, o);
            c += __shfl_down_sync(0xffffffffu, c, o);
        }
        if (threadIdx.x == 0){ g_part[blockIdx.x*2] = a; g_part[blockIdx.x*2+1] = c; }
    }
}

__global__ void k_red2(){
    __shared__ float s1[32], s2[32];
    float s = 0.f, q = 0.f;
    for (int i = threadIdx.x; i < 192; i += 256){ s += g_part[i*2]; q += g_part[i*2+1]; }
    for (int o = 16; o; o >>= 1){
        s += __shfl_down_sync(0xffffffffu, s, o);
        q += __shfl_down_sync(0xffffffffu, q, o);
    }
    if ((threadIdx.x & 31) == 0){ s1[threadIdx.x>>5] = s; s2[threadIdx.x>>5] = q; }
    __syncthreads();
    if (threadIdx.x == 0){
        float a = 0.f, c = 0.f;
        for (int i = 0; i < 8; i++){ a += s1[i]; c += s2[i]; }
        const float T = (float)(NR*VOC);
        float mean = a / T;
        float var  = c / T - mean*mean;
        g_stats[0] = mean;
        g_stats[1] = rsqrtf(var + EPSF);
    }
}

__global__ void k_nrm(){
    int i = blockIdx.x*blockDim.x + threadIdx.x;
    if (i < NR*VOC) h_nrm[i] = __float2half((g_logit[i] - g_stats[0]) * g_stats[1]);
}

__global__ void k_wesum(const float* __restrict__ emb_w){
    int o = threadIdx.x;
    float s = 0.f;
    for (int v = 0; v < VOC; v++) s += emb_w[o*VOC + v];
    g_wesum[o] = s;
}

// ---------------- final expand over f ----------------
__global__ void k_final(const float* __restrict__ bnw, const float* __restrict__ bnb,
                        const float* __restrict__ embb, float* __restrict__ out){
    int i = blockIdx.x*blockDim.x + threadIdx.x;
    const int total = BSZ*5*SEQ*OE;
    if (i >= total) return;
    int o = i & 255;
    int s = (i >> 8) % SEQ;
    int f = (i / (OE*SEQ)) % 5;
    int b = i / (OE*SEQ*5);
    int n = b*SEQ + s;
    out[i] = bnw[f]*g_t[(size_t)n*OE + o] + bnb[f]*g_wesum[o] + embb[o];
}

// ---------------- launch ----------------
extern "C" void kernel_launch(void* const* d_in, const int* in_sizes, int n_in,
                              void* d_out, int out_size)
{
    const float* x        = (const float*)d_in[0];
    const float* in_w     = (const float*)d_in[1];
    const float* conv_w   = (const float*)d_in[2];
    const float* conv_b   = (const float*)d_in[3];
    const float* xp_w     = (const float*)d_in[4];
    const float* dt_w     = (const float*)d_in[5];
    const float* dt_b     = (const float*)d_in[6];
    const float* A_log    = (const float*)d_in[7];
    const float* D_param  = (const float*)d_in[8];
    const float* out_w    = (const float*)d_in[9];
    const float* norm_w   = (const float*)d_in[10];
    const float* normf_w  = (const float*)d_in[11];
    const float* lm_w     = (const float*)d_in[12];
    const float* bn_w     = (const float*)d_in[13];
    const float* bn_b     = (const float*)d_in[14];
    const float* emb_w    = (const float*)d_in[15];
    const float* emb_b    = (const float*)d_in[16];
    float* out = (float*)d_out;

    cudaFuncSetAttribute(k_hmma<4>, cudaFuncAttributeMaxDynamicSharedMemorySize, (int)SMEMH4);
    cudaFuncSetAttribute(k_hmma<2>, cudaFuncAttributeMaxDynamicSharedMemorySize, (int)SMEMH2);

    float *pxz, *pxc, *pdbc, *pdelta, *ph, *plog, *pt, *pnegA;
    __half *qxn, *qinw, *qxct, *qxpw, *qdbc, *qdtw, *qys, *qoutw, *qlmw, *qnrm, *qembw;
    cudaGetSymbolAddress((void**)&ph,     g_h);
    cudaGetSymbolAddress((void**)&pxz,    g_xz);
    cudaGetSymbolAddress((void**)&pxc,    g_xc);
    cudaGetSymbolAddress((void**)&pdbc,   g_dbc);
    cudaGetSymbolAddress((void**)&pdelta, g_delta);
    cudaGetSymbolAddress((void**)&plog,   g_logit);
    cudaGetSymbolAddress((void**)&pt,     g_t);
    cudaGetSymbolAddress((void**)&pnegA,  g_negA);
    cudaGetSymbolAddress((void**)&qxn,    h_xn);
    cudaGetSymbolAddress((void**)&qinw,   h_inw);
    cudaGetSymbolAddress((void**)&qxct,   h_xct);
    cudaGetSymbolAddress((void**)&qxpw,   h_xpw);
    cudaGetSymbolAddress((void**)&qdbc,   h_dbc);
    cudaGetSymbolAddress((void**)&qdtw,   h_dtw);
    cudaGetSymbolAddress((void**)&qys,    h_ys);
    cudaGetSymbolAddress((void**)&qoutw,  h_outw);
    cudaGetSymbolAddress((void**)&qlmw,   h_lmw);
    cudaGetSymbolAddress((void**)&qnrm,   h_nrm);
    cudaGetSymbolAddress((void**)&qembw,  h_embw);

    // launches 0..3: profiled launch (index 3) = big in_proj GEMM
    k_transpose_in<<<(NR*DM + 255)/256, 256>>>(x);                          // 0
    k_cvt2<<<2*2*ED, 256>>>(in_w, qinw, DM, DMP);                           // 1
    k_rmsnorm<<<NR, 256>>>(norm_w);                                         // 2
    k_hmma<4><<<dim3(49, 12), 256, SMEMH4>>>(                               // 3 <- profiled
        qxn, DMP, qinw, DMP, pxz, 2*ED, NR, 2*ED, DMP, 0, nullptr, nullptr, 0);

    // remaining weight conversions
    k_cvt2<<<2*DM, 256>>>(out_w, qoutw, ED, EDP);
    k_cvt2<<<2*DBCN, 256>>>(xp_w, qxpw, ED, EDP);
    k_cvtw<<<(2*ED*DTR + 255)/256, 256>>>(dt_w, qdtw, DTR, DTKP, 2*ED*DTR);
    k_negA<<<(2*ED*DS + 255)/256, 256>>>(A_log);

    for (int l = 0; l < 2; l++){
        if (l == 1){
            k_rmsnorm<<<NR, 256>>>(norm_w + DM);
            k_hmma<4><<<dim3(49, 12), 256, SMEMH4>>>(
                qxn, DMP, qinw + (size_t)2*ED*DMP, DMP, pxz, 2*ED, NR, 2*ED, DMP, 0, nullptr, nullptr, 0);
        }
        k_conv_silu<<<dim3((ED+255)/256, BSZ), 256>>>(conv_w + (size_t)l*ED*4, conv_b + l*ED);
        // dbc = xct @ xp_w^T  (1536 x 129, K=3136)
        k_hmma<2><<<dim3(2, 24), 256, SMEMH2>>>(
            qxct, EDP, qxpw + (size_t)l*DBCN*EDP, EDP, pdbc, DBCP, NR, DBCN, EDP, 3, nullptr, qdbc, DTKP);
        // delta = softplus(dt @ dtw^T + dt_b)  (1536 x 3100, K=128)
        k_hmma<4><<<dim3(25, 12), 256, SMEMH4>>>(
            qdbc, DTKP, qdtw + (size_t)l*ED*DTKP, DTKP, pdelta, ED, NR, ED, DTKP, 2, dt_b + l*ED, nullptr, 0);
        // scan -> h_ys
        k_scan<<<dim3((ED+255)/256, BSZ), 256>>>(pnegA + (size_t)l*ED*DS, D_param + l*ED);
        // h += ys @ out_w^T  (1536 x 1550, K=3136)
        k_hmma<4><<<dim3(13, 12), 256, SMEMH4>>>(
            qys, EDP, qoutw + (size_t)l*DM*EDP, EDP, ph, DM, NR, DM, EDP, 1, nullptr, nullptr, 0);
    }

    k_rmsnorm<<<NR, 256>>>(normf_w);
    k_cvt2<<<VOC, 256>>>(lm_w, qlmw, DM, DMP);
    // logits = xn @ lm_w^T  (1536 x 128, K=1600)
    k_hmma<2><<<dim3(1, 24), 256, SMEMH2>>>(
        qxn, DMP, qlmw, DMP, plog, VOC, NR, VOC, DMP, 0, nullptr, nullptr, 0);
    k_red1<<<192, 256>>>();
    k_red2<<<1, 256>>>();
    k_nrm<<<(NR*VOC + 255)/256, 256>>>();
    k_cvt2<<<OE, 256>>>(emb_w, qembw, VOC, VOC);
    // t = nrm @ emb_w^T  (1536 x 256, K=128)
    k_hmma<2><<<dim3(2, 24), 256, SMEMH2>>>(
        qnrm, VOC, qembw, VOC, pt, OE, NR, OE, VOC, 0, nullptr, nullptr, 0);
    k_wesum<<<1, 256>>>(emb_w);
    k_final<<<(BSZ*5*SEQ*OE + 255)/256, 256>>>(bn_w, bn_b, emb_b, out);
}

// round 8
// speedup vs baseline: 3.0591x; 1.0185x over previous
#include <cuda_runtime.h>
#include <cuda_fp16.h>
#include <math.h>
#include <stdint.h>

// ---------------- problem constants ----------------
#define BSZ   512
#define SEQ   3
#define DM    1550
#define DMP   1600          // DM padded to x64
#define DS    16
#define ED    3100
#define EDP   3136          // ED padded to x64
#define DTR   97
#define DTKP  128           // dt GEMM K padded
#define DBCN  129
#define DBCP  132           // fp32 dbc ldc
#define VOC   128
#define NR    (BSZ*SEQ)
#define OE    256
#define EPSF  1e-5f

#define SROW  72            // smem row stride in halves (BK=64 + 8 pad)
#define NSTG  3             // pipeline stages

// ---------------- fp32 scratch ----------------
__device__ __align__(256) float g_h    [NR*DM];
__device__ __align__(256) float g_xz   [NR*2*ED];
__device__ __align__(256) float g_xc   [NR*ED];
__device__ __align__(256) float g_dbc  [NR*DBCP];
__device__ __align__(256) float g_delta[NR*ED];
__device__ __align__(256) float g_negA [2*ED*DS];
__device__ __align__(256) float g_logit[NR*VOC];
__device__ __align__(256) float g_t    [NR*OE];
__device__ float g_part [384];
__device__ float g_stats[2];
__device__ float g_wesum[OE];

// ---------------- fp16 GEMM operand scratch (zero-init pads) ----------------
__device__ __align__(256) __half h_xn  [NR*DMP];
__device__ __align__(256) __half h_inw [2*2*ED*DMP];
__device__ __align__(256) __half h_xct [NR*EDP];
__device__ __align__(256) __half h_xpw [2*DBCN*EDP];
__device__ __align__(256) __half h_dbc [NR*DTKP];
__device__ __align__(256) __half h_dtw [2*ED*DTKP];
__device__ __align__(256) __half h_ys  [NR*EDP];
__device__ __align__(256) __half h_outw[2*DM*EDP];
__device__ __align__(256) __half h_lmw [VOC*DMP];
__device__ __align__(256) __half h_nrm [NR*VOC];
__device__ __align__(256) __half h_embw[OE*VOC];

__device__ __forceinline__ float siluf(float v){ return v / (1.f + expf(-v)); }

__device__ __forceinline__ void mma_f16(float c[4],
    uint32_t a0, uint32_t a1, uint32_t a2, uint32_t a3,
    uint32_t b0, uint32_t b1)
{
    asm volatile(
        "mma.sync.aligned.m16n8k16.row.col.f32.f16.f16.f32 "
        "{%0,%1,%2,%3}, {%4,%5,%6,%7}, {%8,%9}, {%0,%1,%2,%3};"
        : "+f"(c[0]), "+f"(c[1]), "+f"(c[2]), "+f"(c[3])
        : "r"(a0), "r"(a1), "r"(a2), "r"(a3), "r"(b0), "r"(b1));
}

__device__ __forceinline__ void cpa16(uint32_t sdst, const __half* gsrc, int nbytes){
    asm volatile("cp.async.cg.shared.global [%0], [%1], 16, %2;"
                 :: "r"(sdst), "l"(gsrc), "r"(nbytes));
}

__device__ __forceinline__ void ldsm4(uint32_t r[4], uint32_t addr){
    asm volatile("ldmatrix.sync.aligned.m8n8.x4.shared.b16 {%0,%1,%2,%3}, [%4];"
        : "=r"(r[0]), "=r"(r[1]), "=r"(r[2]), "=r"(r[3]) : "r"(addr));
}

// ---------------- FP16 tensor-core GEMM, BK=64, 3-stage cp.async, ldmatrix ----------------
// C[M,N] (op)= A[M,K] * B[N,K]^T. fp16 operands, fp32 accum.
// MT=4 -> BM=128 ; MT=2 -> BM=64. BN=128, BK=64.
// Requirements: M % BM == 0; K % 64 == 0 and K >= 128; lda, ldb % 8 == 0.
// mode 0: C = acc ; 1: C += acc ; 2: C = softplus(acc + bias[n]) ;
// mode 3: C = acc AND Ch[r*ldch+c] = half(acc) for c < DTR.
template<int MT>
__global__ void __launch_bounds__(256, 2) k_hmma(
    const __half* __restrict__ A, int lda,
    const __half* __restrict__ B, int ldb,
    float* __restrict__ C, int ldc,
    int M, int N, int K,
    int mode, const float* __restrict__ bias,
    __half* __restrict__ Ch, int ldch)
{
    constexpr int BM = MT*32;
    extern __shared__ __half smh[];
    __half* As = smh;                       // [NSTG][BM][SROW]
    __half* Bs = smh + NSTG*BM*SROW;        // [NSTG][128][SROW]

    const int tid  = threadIdx.x;
    const int wid  = tid >> 5, lane = tid & 31;
    const int g    = lane >> 2, tg = lane & 3;
    const int wm   = (wid >> 2) * (MT*16);
    const int wn   = (wid & 3) * 32;
    const int bm   = blockIdx.y * BM;
    const int bn   = blockIdx.x * 128;

    const int lrow = tid >> 3;           // 0..31 (loader row)
    const int lcol = (tid & 7) * 8;      // half offset of 16B slot in 64-wide row

    const uint32_t sA = (uint32_t)__cvta_generic_to_shared(As);
    const uint32_t sB = (uint32_t)__cvta_generic_to_shared(Bs);

    // ldmatrix lane addresses (stage 0, kst 0)
    uint32_t aaddr[MT], baddr[2];
    {
        int arow = wm + (lane & 15);
        int acol = ((lane >> 4) & 1) * 8;
        #pragma unroll
        for (int mt = 0; mt < MT; mt++)
            aaddr[mt] = sA + (uint32_t)(((arow + mt*16)*SROW + acol)*2);
        #pragma unroll
        for (int ntp = 0; ntp < 2; ntp++){
            int brow = wn + ntp*16 + (lane & 7) + ((lane >> 4) & 1)*8;
            int bcol = ((lane >> 3) & 1) * 8;
            baddr[ntp] = sB + (uint32_t)((brow*SROW + bcol)*2);
        }
    }

    float acc[MT][4][4];
    #pragma unroll
    for (int mt = 0; mt < MT; mt++)
        #pragma unroll
        for (int nt = 0; nt < 4; nt++)
            #pragma unroll
            for (int i = 0; i < 4; i++) acc[mt][nt][i] = 0.f;

    const int nch = K >> 6;

    auto issue = [&](int c){
        const int gk = c*64 + lcol;
        const int s  = c % NSTG;
        uint32_t da = sA + (uint32_t)((s*BM*SROW + lrow*SROW + lcol)*2);
        #pragma unroll
        for (int p = 0; p < BM/32; p++)
            cpa16(da + (uint32_t)(p*32*SROW*2),
                  A + (size_t)(bm + lrow + p*32)*lda + gk, 16);
        uint32_t db = sB + (uint32_t)((s*128*SROW + lrow*SROW + lcol)*2);
        #pragma unroll
        for (int p = 0; p < 4; p++){
            int gn = bn + lrow + p*32;
            cpa16(db + (uint32_t)(p*32*SROW*2),
                  B + (size_t)(gn < N ? gn : 0)*ldb + gk, (gn < N) ? 16 : 0);
        }
        asm volatile("cp.async.commit_group;");
    };

    issue(0);
    issue(1);
    for (int c = 0; c < nch; c++){
        if (c + 1 < nch) asm volatile("cp.async.wait_group 1;");
        else             asm volatile("cp.async.wait_group 0;");
        __syncthreads();
        if (c + 2 < nch) issue(c + 2);

        const uint32_t offA = (uint32_t)((c % NSTG)*BM*SROW*2);
        const uint32_t offB = (uint32_t)((c % NSTG)*128*SROW*2);
        #pragma unroll
        for (int kst = 0; kst < 4; kst++){
            uint32_t af[MT][4], bfr[2][4];
            #pragma unroll
            for (int mt = 0; mt < MT; mt++)
                ldsm4(af[mt], aaddr[mt] + offA + kst*32);
            #pragma unroll
            for (int ntp = 0; ntp < 2; ntp++)
                ldsm4(bfr[ntp], baddr[ntp] + offB + kst*32);
            #pragma unroll
            for (int mt = 0; mt < MT; mt++)
                #pragma unroll
                for (int nt = 0; nt < 4; nt++)
                    mma_f16(acc[mt][nt],
                            af[mt][0], af[mt][1], af[mt][2], af[mt][3],
                            bfr[nt >> 1][(nt & 1)*2], bfr[nt >> 1][(nt & 1)*2 + 1]);
        }
    }

    // ---- epilogue ----
    #pragma unroll
    for (int mt = 0; mt < MT; mt++){
        int r0 = bm + wm + mt*16 + g;
        #pragma unroll
        for (int nt = 0; nt < 4; nt++){
            int cl = bn + wn + nt*8 + 2*tg;
            #pragma unroll
            for (int i = 0; i < 4; i++){
                int rr = r0 + (i >> 1)*8;
                int cc = cl + (i & 1);
                if (cc >= N) continue;
                float v = acc[mt][nt][i];
                size_t idx = (size_t)rr*ldc + cc;
                if (mode == 1){
                    v += C[idx];
                } else if (mode == 2){
                    float xv = v + bias[cc];
                    v = fmaxf(xv, 0.f) + log1pf(expf(-fabsf(xv)));
                } else if (mode == 3){
                    if (cc < DTR) Ch[(size_t)rr*ldch + cc] = __float2half(v);
                }
                C[idx] = v;
            }
        }
    }
}

#define SMEMH4 (NSTG*(128+128)*SROW*sizeof(__half))   // 110592
#define SMEMH2 (NSTG*(64 +128)*SROW*sizeof(__half))   // 82944

// ---------------- vectorized fp32 -> padded fp16 (one block per row, K even) ----------------
__global__ void k_cvt2(const float* __restrict__ src, __half* __restrict__ dst,
                       int K, int KP){
    int r = blockIdx.x;
    const float2* s = (const float2*)(src + (size_t)r*K);
    __half* d = dst + (size_t)r*KP;
    const int n2 = K >> 1;
    for (int i = threadIdx.x; i < n2; i += blockDim.x){
        float2 v = s[i];
        *(__half2*)(d + 2*i) = __floats2half2_rn(v.x, v.y);
    }
}

// scalar pad conversion for odd-K dt_w
__global__ void k_cvtw(const float* __restrict__ src, __half* __restrict__ dst,
                       int K, int KP, int n){
    int i = blockIdx.x*blockDim.x + threadIdx.x;
    if (i < n) dst[(size_t)(i/K)*KP + (i%K)] = __float2half(src[i]);
}

// ---------------- input transpose ----------------
__global__ void k_transpose_in(const float* __restrict__ x){
    int i = blockIdx.x*blockDim.x + threadIdx.x;
    if (i >= NR*DM) return;
    int n = i / DM, d = i % DM;
    int c = d / 25, r = d % 25, f = r / 5, e = r % 5;
    g_h[i] = x[((n*5 + f)*62 + c)*5 + e];
}

// ---------------- rmsnorm: g_h -> h_xn (fp16, padded) ----------------
__global__ void k_rmsnorm(const float* __restrict__ w){
    __shared__ float sh[33];
    int n = blockIdx.x;
    const float* row = g_h + (size_t)n*DM;
    float ss = 0.f;
    for (int d = threadIdx.x; d < DM; d += blockDim.x){ float v = row[d]; ss += v*v; }
    for (int o = 16; o; o >>= 1) ss += __shfl_down_sync(0xffffffffu, ss, o);
    if ((threadIdx.x & 31) == 0) sh[threadIdx.x >> 5] = ss;
    __syncthreads();
    if (threadIdx.x < 32){
        float v = (threadIdx.x < (int)(blockDim.x >> 5)) ? sh[threadIdx.x] : 0.f;
        for (int o = 16; o; o >>= 1) v += __shfl_down_sync(0xffffffffu, v, o);
        if (threadIdx.x == 0) sh[32] = rsqrtf(v / (float)DM + EPSF);
    }
    __syncthreads();
    float sc = sh[32];
    for (int d = threadIdx.x; d < DM; d += blockDim.x)
        h_xn[(size_t)n*DMP + d] = __float2half(row[d] * sc * w[d]);
}

// ---------------- depthwise causal conv + silu; fp32 exact + fp16 copy ----------------
__global__ void k_conv_silu(const float* __restrict__ cw, const float* __restrict__ cb){
    int e = blockIdx.x*blockDim.x + threadIdx.x;
    int b = blockIdx.y;
    if (e >= ED) return;
    size_t r0 = (size_t)(b*SEQ + 0)*(2*ED);
    size_t r1 = (size_t)(b*SEQ + 1)*(2*ED);
    size_t r2 = (size_t)(b*SEQ + 2)*(2*ED);
    float x0 = g_xz[r0 + e], x1 = g_xz[r1 + e], x2 = g_xz[r2 + e];
    float w1 = cw[e*4+1], w2 = cw[e*4+2], w3 = cw[e*4+3];
    float bb = cb[e];
    float y0 = siluf(bb + w3*x0);
    float y1 = siluf(bb + w2*x0 + w3*x1);
    float y2 = siluf(bb + w1*x0 + w2*x1 + w3*x2);
    g_xc[(size_t)(b*SEQ + 0)*ED + e] = y0;  h_xct[(size_t)(b*SEQ + 0)*EDP + e] = __float2half(y0);
    g_xc[(size_t)(b*SEQ + 1)*ED + e] = y1;  h_xct[(size_t)(b*SEQ + 1)*EDP + e] = __float2half(y1);
    g_xc[(size_t)(b*SEQ + 2)*ED + e] = y2;  h_xct[(size_t)(b*SEQ + 2)*EDP + e] = __float2half(y2);
}

// ---------------- negA (both layers) ----------------
__global__ void k_negA(const float* __restrict__ Alog){
    int i = blockIdx.x*blockDim.x + threadIdx.x;
    if (i < 2*ED*DS) g_negA[i] = -expf(Alog[i]);
}

// ---------------- fused SSM scan (S=3), + D*xc, * silu(z) -> h_ys fp16 ----------------
__global__ void k_scan(const float* __restrict__ nAbase, const float* __restrict__ Dp){
    __shared__ float sB[SEQ][DS], sC[SEQ][DS];
    int e = blockIdx.x*blockDim.x + threadIdx.x;
    int b = blockIdx.y;
    int t = threadIdx.x;
    if (t < SEQ*DS){
        int s = t / DS, n = t % DS;
        size_t base = (size_t)(b*SEQ + s)*DBCP + DTR;
        sB[s][n] = g_dbc[base + n];
        sC[s][n] = g_dbc[base + DS + n];
    }
    __syncthreads();
    if (e >= ED) return;

    float nA[DS], hst[DS];
    #pragma unroll
    for (int n = 0; n < DS; n++){ nA[n] = nAbase[e*DS + n]; hst[n] = 0.f; }
    float dpe = Dp[e];

    #pragma unroll
    for (int s = 0; s < SEQ; s++){
        size_t row = (size_t)(b*SEQ + s);
        float d   = g_delta[row*ED + e];
        float xcv = g_xc[row*ED + e];
        float dx  = d * xcv;
        float y = 0.f;
        #pragma unroll
        for (int n = 0; n < DS; n++){
            float dA = __expf(d * nA[n]);
            hst[n] = dA*hst[n] + dx*sB[s][n];
            y = fmaf(hst[n], sC[s][n], y);
        }
        y += dpe * xcv;
        float z = g_xz[row*(2*ED) + ED + e];
        h_ys[row*EDP + e] = __float2half(y * siluf(z));
    }
}

// ---------------- logits mean/var (deterministic 2-pass) ----------------
__global__ void k_red1(){
    __shared__ float s1[32], s2[32];
    int base = blockIdx.x * 1024;
    float s = 0.f, q = 0.f;
    for (int i = threadIdx.x; i < 1024; i += 256){
        float v = g_logit[base + i];
        s += v; q += v*v;
    }
    for (int o = 16; o; o >>= 1){
        s += __shfl_down_sync(0xffffffffu, s, o);
        q += __shfl_down_sync(0xffffffffu, q, o);
    }
    if ((threadIdx.x & 31) == 0){ s1[threadIdx.x>>5] = s; s2[threadIdx.x>>5] = q; }
    __syncthreads();
    if (threadIdx.x < 32){
        float a = (threadIdx.x < 8) ? s1[threadIdx.x] : 0.f;
        float c = (threadIdx.x < 8) ? s2[threadIdx.x] : 0.f;
        for (int o = 4; o; o >>= 1){
            a += __shfl_down_sync(0xffffffffu, a, o);
            c += __shfl_down_sync(0xffffffffu, c, o);
        }
        if (threadIdx.x == 0){ g_part[blockIdx.x*2] = a; g_part[blockIdx.x*2+1] = c; }
    }
}

__global__ void k_red2(){
    __shared__ float s1[32], s2[32];
    float s = 0.f, q = 0.f;
    for (int i = threadIdx.x; i < 192; i += 256){ s += g_part[i*2]; q += g_part[i*2+1]; }
    for (int o = 16; o; o >>= 1){
        s += __shfl_down_sync(0xffffffffu, s, o);
        q += __shfl_down_sync(0xffffffffu, q, o);
    }
    if ((threadIdx.x & 31) == 0){ s1[threadIdx.x>>5] = s; s2[threadIdx.x>>5] = q; }
    __syncthreads();
    if (threadIdx.x == 0){
        float a = 0.f, c = 0.f;
        for (int i = 0; i < 8; i++){ a += s1[i]; c += s2[i]; }
        const float T = (float)(NR*VOC);
        float mean = a / T;
        float var  = c / T - mean*mean;
        g_stats[0] = mean;
        g_stats[1] = rsqrtf(var + EPSF);
    }
}

__global__ void k_nrm(){
    int i = blockIdx.x*blockDim.x + threadIdx.x;
    if (i < NR*VOC) h_nrm[i] = __float2half((g_logit[i] - g_stats[0]) * g_stats[1]);
}

__global__ void k_wesum(const float* __restrict__ emb_w){
    int o = threadIdx.x;
    float s = 0.f;
    for (int v = 0; v < VOC; v++) s += emb_w[o*VOC + v];
    g_wesum[o] = s;
}

// ---------------- final expand over f ----------------
__global__ void k_final(const float* __restrict__ bnw, const float* __restrict__ bnb,
                        const float* __restrict__ embb, float* __restrict__ out){
    int i = blockIdx.x*blockDim.x + threadIdx.x;
    const int total = BSZ*5*SEQ*OE;
    if (i >= total) return;
    int o = i & 255;
    int s = (i >> 8) % SEQ;
    int f = (i / (OE*SEQ)) % 5;
    int b = i / (OE*SEQ*5);
    int n = b*SEQ + s;
    out[i] = bnw[f]*g_t[(size_t)n*OE + o] + bnb[f]*g_wesum[o] + embb[o];
}

// ---------------- launch ----------------
extern "C" void kernel_launch(void* const* d_in, const int* in_sizes, int n_in,
                              void* d_out, int out_size)
{
    const float* x        = (const float*)d_in[0];
    const float* in_w     = (const float*)d_in[1];
    const float* conv_w   = (const float*)d_in[2];
    const float* conv_b   = (const float*)d_in[3];
    const float* xp_w     = (const float*)d_in[4];
    const float* dt_w     = (const float*)d_in[5];
    const float* dt_b     = (const float*)d_in[6];
    const float* A_log    = (const float*)d_in[7];
    const float* D_param  = (const float*)d_in[8];
    const float* out_w    = (const float*)d_in[9];
    const float* norm_w   = (const float*)d_in[10];
    const float* normf_w  = (const float*)d_in[11];
    const float* lm_w     = (const float*)d_in[12];
    const float* bn_w     = (const float*)d_in[13];
    const float* bn_b     = (const float*)d_in[14];
    const float* emb_w    = (const float*)d_in[15];
    const float* emb_b    = (const float*)d_in[16];
    float* out = (float*)d_out;

    cudaFuncSetAttribute(k_hmma<4>, cudaFuncAttributeMaxDynamicSharedMemorySize, (int)SMEMH4);
    cudaFuncSetAttribute(k_hmma<2>, cudaFuncAttributeMaxDynamicSharedMemorySize, (int)SMEMH2);

    float *pxz, *pxc, *pdbc, *pdelta, *ph, *plog, *pt, *pnegA;
    __half *qxn, *qinw, *qxct, *qxpw, *qdbc, *qdtw, *qys, *qoutw, *qlmw, *qnrm, *qembw;
    cudaGetSymbolAddress((void**)&ph,     g_h);
    cudaGetSymbolAddress((void**)&pxz,    g_xz);
    cudaGetSymbolAddress((void**)&pxc,    g_xc);
    cudaGetSymbolAddress((void**)&pdbc,   g_dbc);
    cudaGetSymbolAddress((void**)&pdelta, g_delta);
    cudaGetSymbolAddress((void**)&plog,   g_logit);
    cudaGetSymbolAddress((void**)&pt,     g_t);
    cudaGetSymbolAddress((void**)&pnegA,  g_negA);
    cudaGetSymbolAddress((void**)&qxn,    h_xn);
    cudaGetSymbolAddress((void**)&qinw,   h_inw);
    cudaGetSymbolAddress((void**)&qxct,   h_xct);
    cudaGetSymbolAddress((void**)&qxpw,   h_xpw);
    cudaGetSymbolAddress((void**)&qdbc,   h_dbc);
    cudaGetSymbolAddress((void**)&qdtw,   h_dtw);
    cudaGetSymbolAddress((void**)&qys,    h_ys);
    cudaGetSymbolAddress((void**)&qoutw,  h_outw);
    cudaGetSymbolAddress((void**)&qlmw,   h_lmw);
    cudaGetSymbolAddress((void**)&qnrm,   h_nrm);
    cudaGetSymbolAddress((void**)&qembw,  h_embw);

    // launches 0..3: profiled launch (index 3) = big in_proj GEMM
    k_transpose_in<<<(NR*DM + 255)/256, 256>>>(x);                          // 0
    k_cvt2<<<2*2*ED, 256>>>(in_w, qinw, DM, DMP);                           // 1
    k_rmsnorm<<<NR, 256>>>(norm_w);                                         // 2
    k_hmma<4><<<dim3(49, 12), 256, SMEMH4>>>(                               // 3 <- profiled
        qxn, DMP, qinw, DMP, pxz, 2*ED, NR, 2*ED, DMP, 0, nullptr, nullptr, 0);

    // remaining weight conversions
    k_cvt2<<<2*DM, 256>>>(out_w, qoutw, ED, EDP);
    k_cvt2<<<2*DBCN, 256>>>(xp_w, qxpw, ED, EDP);
    k_cvtw<<<(2*ED*DTR + 255)/256, 256>>>(dt_w, qdtw, DTR, DTKP, 2*ED*DTR);
    k_negA<<<(2*ED*DS + 255)/256, 256>>>(A_log);

    for (int l = 0; l < 2; l++){
        if (l == 1){
            k_rmsnorm<<<NR, 256>>>(norm_w + DM);
            k_hmma<4><<<dim3(49, 12), 256, SMEMH4>>>(
                qxn, DMP, qinw + (size_t)2*ED*DMP, DMP, pxz, 2*ED, NR, 2*ED, DMP, 0, nullptr, nullptr, 0);
        }
        k_conv_silu<<<dim3((ED+255)/256, BSZ), 256>>>(conv_w + (size_t)l*ED*4, conv_b + l*ED);
        // dbc = xct @ xp_w^T  (1536 x 129, K=3136)
        k_hmma<2><<<dim3(2, 24), 256, SMEMH2>>>(
            qxct, EDP, qxpw + (size_t)l*DBCN*EDP, EDP, pdbc, DBCP, NR, DBCN, EDP, 3, nullptr, qdbc, DTKP);
        // delta = softplus(dt @ dtw^T + dt_b)  (1536 x 3100, K=128)
        k_hmma<4><<<dim3(25, 12), 256, SMEMH4>>>(
            qdbc, DTKP, qdtw + (size_t)l*ED*DTKP, DTKP, pdelta, ED, NR, ED, DTKP, 2, dt_b + l*ED, nullptr, 0);
        // scan -> h_ys
        k_scan<<<dim3((ED+255)/256, BSZ), 256>>>(pnegA + (size_t)l*ED*DS, D_param + l*ED);
        // h += ys @ out_w^T  (1536 x 1550, K=3136)
        k_hmma<4><<<dim3(13, 12), 256, SMEMH4>>>(
            qys, EDP, qoutw + (size_t)l*DM*EDP, EDP, ph, DM, NR, DM, EDP, 1, nullptr, nullptr, 0);
    }

    k_rmsnorm<<<NR, 256>>>(normf_w);
    k_cvt2<<<VOC, 256>>>(lm_w, qlmw, DM, DMP);
    // logits = xn @ lm_w^T  (1536 x 128, K=1600)
    k_hmma<2><<<dim3(1, 24), 256, SMEMH2>>>(
        qxn, DMP, qlmw, DMP, plog, VOC, NR, VOC, DMP, 0, nullptr, nullptr, 0);
    k_red1<<<192, 256>>>();
    k_red2<<<1, 256>>>();
    k_nrm<<<(NR*VOC + 255)/256, 256>>>();
    k_cvt2<<<OE, 256>>>(emb_w, qembw, VOC, VOC);
    // t = nrm @ emb_w^T  (1536 x 256, K=128)
    k_hmma<2><<<dim3(2, 24), 256, SMEMH2>>>(
        qnrm, VOC, qembw, VOC, pt, OE, NR, OE, VOC, 0, nullptr, nullptr, 0);
    k_wesum<<<1, 256>>>(emb_w);
    k_final<<<(BSZ*5*SEQ*OE + 255)/256, 256>>>(bn_w, bn_b, emb_b, out);
}